// round 1
// baseline (speedup 1.0000x reference)
#include <cuda_runtime.h>

#define D 64
#define MAXN 150208   // multiple of 64, >= 150000

// ---- scratch (static device arrays: allocation-free) ----
__device__ float g_out1[(size_t)MAXN * D];   // conv1 output
__device__ float g_sum[D];
__device__ float g_sq[D];
__device__ float g_scale[D];
__device__ float g_shift[D];

__global__ void zero_stats_kernel() {
    int t = threadIdx.x;
    if (t < D) { g_sum[t] = 0.f; g_sq[t] = 0.f; }
}

// ============================================================
// conv1: out1[n,:] = sum_k mask[k,n] ? x[idx[k,n],:] @ W1[k] : 0
// 64-row x 64-col tile per block, 256 threads, 4x4 per-thread micro-tile.
// Also accumulates per-channel sum / sum-of-squares for BN.
// ============================================================
__global__ __launch_bounds__(256) void conv1_kernel(
    const float* __restrict__ x,
    const int*   __restrict__ nbr_idx,
    const int*   __restrict__ nbr_mask,
    const float* __restrict__ W1,
    int N, int K)
{
    __shared__ __align__(16) float Ws[D * D];       // W1[k], [j][c]
    __shared__ __align__(16) float Gs[64 * 68];     // gathered rows, stride 68
    __shared__ float s_sum[D], s_sq[D];

    const int tid = threadIdx.x;
    const int tx  = tid & 15;
    const int ty  = tid >> 4;
    const int row0 = blockIdx.x * 64;

    if (tid < D) { s_sum[tid] = 0.f; s_sq[tid] = 0.f; }

    float acc[4][4];
#pragma unroll
    for (int i = 0; i < 4; ++i)
#pragma unroll
        for (int ii = 0; ii < 4; ++ii) acc[i][ii] = 0.f;

    const int grow  = row0 + (tid >> 2);   // row this thread gathers
    const int chunk = (tid & 3) * 16;      // 16-float chunk within the row
    const int r     = tid >> 2;

    for (int k = 0; k < K; ++k) {
        // ---- load W1[k] (16 KB) cooperatively ----
        const float4* wsrc = (const float4*)(W1 + (size_t)k * D * D);
        float4* wdst = (float4*)Ws;
#pragma unroll
        for (int t = 0; t < 4; ++t)
            wdst[tid + t * 256] = wsrc[tid + t * 256];

        // ---- masked gather of 64 rows into Gs ----
        int m = 0;
        size_t src = 0;
        if (grow < N) {
            m = nbr_mask[(size_t)k * N + grow];
            if (m) src = (size_t)nbr_idx[(size_t)k * N + grow] * D;
        }
        float4* gdst = (float4*)(Gs + r * 68 + chunk);
        if (m) {
            const float4* gsrc = (const float4*)(x + src + chunk);
#pragma unroll
            for (int t = 0; t < 4; ++t) gdst[t] = gsrc[t];
        } else {
            float4 z = make_float4(0.f, 0.f, 0.f, 0.f);
#pragma unroll
            for (int t = 0; t < 4; ++t) gdst[t] = z;
        }
        __syncthreads();

        // ---- 64x64x64 GEMM accumulate ----
#pragma unroll 16
        for (int j = 0; j < D; ++j) {
            float4 b = *(const float4*)(Ws + j * D + tx * 4);
#pragma unroll
            for (int i = 0; i < 4; ++i) {
                float a = Gs[(ty * 4 + i) * 68 + j];
                acc[i][0] += a * b.x;
                acc[i][1] += a * b.y;
                acc[i][2] += a * b.z;
                acc[i][3] += a * b.w;
            }
        }
        __syncthreads();
    }

    // ---- per-channel stats (rows >= N hold zeros -> contribute nothing) ----
#pragma unroll
    for (int ii = 0; ii < 4; ++ii) {
        float cs = 0.f, cq = 0.f;
#pragma unroll
        for (int i = 0; i < 4; ++i) { float v = acc[i][ii]; cs += v; cq += v * v; }
        atomicAdd(&s_sum[tx * 4 + ii], cs);
        atomicAdd(&s_sq [tx * 4 + ii], cq);
    }

    // ---- store tile ----
#pragma unroll
    for (int i = 0; i < 4; ++i) {
        int row = row0 + ty * 4 + i;
        if (row < N) {
            float4 v = make_float4(acc[i][0], acc[i][1], acc[i][2], acc[i][3]);
            *(float4*)(g_out1 + (size_t)row * D + tx * 4) = v;
        }
    }
    __syncthreads();
    if (tid < D) {
        atomicAdd(&g_sum[tid], s_sum[tid]);
        atomicAdd(&g_sq [tid], s_sq [tid]);
    }
}

// ============================================================
// finalize: fold BN into per-channel scale/shift
// ============================================================
__global__ void finalize_kernel(const float* __restrict__ gamma,
                                const float* __restrict__ beta,
                                float invN)
{
    int c = threadIdx.x;
    if (c < D) {
        float mean = g_sum[c] * invN;
        float var  = g_sq[c] * invN - mean * mean;
        float rstd = rsqrtf(var + 1e-5f);
        float sc   = rstd * gamma[c];
        g_scale[c] = sc;
        g_shift[c] = beta[c] - mean * sc;
    }
}

// ============================================================
// fused: h = BN(out1); out = relu(h @ W2) @ W3 + x
// 64-row tile, 256 threads, 4x4 micro-tiles, chunked over the 256-dim.
// smem (dynamic, 68096 B): Hs[64*68] Tc[64*68] Wb2[64*64] Wb3[64*64] sc sh
// ============================================================
__global__ __launch_bounds__(256) void mlp_kernel(
    const float* __restrict__ x,
    const float* __restrict__ W2,
    const float* __restrict__ W3,
    float* __restrict__ out,
    int N)
{
    extern __shared__ __align__(16) float smem[];
    float* Hs  = smem;                 // 64*68
    float* Tc  = Hs  + 64 * 68;       // 64*68
    float* Wb2 = Tc  + 64 * 68;       // 64*64
    float* Wb3 = Wb2 + 64 * 64;       // 64*64
    float* sc  = Wb3 + 64 * 64;       // 64
    float* sh  = sc + 64;             // 64

    const int tid = threadIdx.x;
    const int tx  = tid & 15;
    const int ty  = tid >> 4;
    const int row0 = blockIdx.x * 64;

    if (tid < D) { sc[tid] = g_scale[tid]; sh[tid] = g_shift[tid]; }
    __syncthreads();

    // load tile with BN applied
    {
        int r  = tid >> 2;
        int c0 = (tid & 3) * 16;
        int row = row0 + r;
#pragma unroll
        for (int t = 0; t < 16; ++t) {
            int c = c0 + t;
            float v = (row < N) ? g_out1[(size_t)row * D + c] : 0.f;
            Hs[r * 68 + c] = v * sc[c] + sh[c];
        }
    }

    float acc2[4][4];
#pragma unroll
    for (int i = 0; i < 4; ++i)
#pragma unroll
        for (int ii = 0; ii < 4; ++ii) acc2[i][ii] = 0.f;

    for (int cb = 0; cb < 4; ++cb) {
        const int c0 = cb * 64;

        // load W2[:, c0:c0+64]
#pragma unroll
        for (int t = 0; t < 4; ++t) {
            int f  = tid + t * 256;      // float4 id 0..1023
            int j  = f >> 4;             // source row in W2
            int c4 = (f & 15) << 2;      // local col (floats)
            *(float4*)(Wb2 + j * 64 + c4) =
                *(const float4*)(W2 + (size_t)j * 256 + c0 + c4);
        }
        __syncthreads();   // Hs + Wb2 ready

        // GEMM1 chunk: Hs @ Wb2
        float acc1[4][4];
#pragma unroll
        for (int i = 0; i < 4; ++i)
#pragma unroll
            for (int ii = 0; ii < 4; ++ii) acc1[i][ii] = 0.f;

#pragma unroll 16
        for (int j = 0; j < 64; ++j) {
            float4 b = *(const float4*)(Wb2 + j * 64 + tx * 4);
#pragma unroll
            for (int i = 0; i < 4; ++i) {
                float a = Hs[(ty * 4 + i) * 68 + j];
                acc1[i][0] += a * b.x;
                acc1[i][1] += a * b.y;
                acc1[i][2] += a * b.z;
                acc1[i][3] += a * b.w;
            }
        }

        // ReLU -> Tc
#pragma unroll
        for (int i = 0; i < 4; ++i) {
            float4 v = make_float4(fmaxf(acc1[i][0], 0.f), fmaxf(acc1[i][1], 0.f),
                                   fmaxf(acc1[i][2], 0.f), fmaxf(acc1[i][3], 0.f));
            *(float4*)(Tc + (ty * 4 + i) * 68 + tx * 4) = v;
        }

        // load W3[c0:c0+64, :] (contiguous 16 KB)
#pragma unroll
        for (int t = 0; t < 4; ++t) {
            int f = tid + t * 256;
            ((float4*)Wb3)[f] = ((const float4*)(W3 + (size_t)c0 * 64))[f];
        }
        __syncthreads();   // Tc + Wb3 ready

        // GEMM2 chunk accumulate: Tc @ Wb3
#pragma unroll 16
        for (int j = 0; j < 64; ++j) {
            float4 b = *(const float4*)(Wb3 + j * 64 + tx * 4);
#pragma unroll
            for (int i = 0; i < 4; ++i) {
                float a = Tc[(ty * 4 + i) * 68 + j];
                acc2[i][0] += a * b.x;
                acc2[i][1] += a * b.y;
                acc2[i][2] += a * b.z;
                acc2[i][3] += a * b.w;
            }
        }
        __syncthreads();   // protect Wb2/Tc for next chunk
    }

    // residual + store
#pragma unroll
    for (int i = 0; i < 4; ++i) {
        int row = row0 + ty * 4 + i;
        if (row < N) {
            float4 xv = *(const float4*)(x + (size_t)row * D + tx * 4);
            float4 o  = make_float4(acc2[i][0] + xv.x, acc2[i][1] + xv.y,
                                    acc2[i][2] + xv.z, acc2[i][3] + xv.w);
            *(float4*)(out + (size_t)row * D + tx * 4) = o;
        }
    }
}

// ============================================================
// launch
// ============================================================
extern "C" void kernel_launch(void* const* d_in, const int* in_sizes, int n_in,
                              void* d_out, int out_size)
{
    const float* x     = (const float*)d_in[0];
    const int*   nidx  = (const int*)  d_in[1];
    const int*   nmask = (const int*)  d_in[2];
    const float* W1    = (const float*)d_in[3];
    const float* gamma = (const float*)d_in[4];
    const float* beta  = (const float*)d_in[5];
    const float* W2    = (const float*)d_in[6];
    const float* W3    = (const float*)d_in[7];
    float* out = (float*)d_out;

    const int N = in_sizes[0] / D;
    const int K = in_sizes[1] / N;
    const int nblk = (N + 63) / 64;

    const int smem3 = (64 * 68 * 2 + 64 * 64 * 2 + 128) * (int)sizeof(float);
    cudaFuncSetAttribute(mlp_kernel, cudaFuncAttributeMaxDynamicSharedMemorySize, smem3);

    zero_stats_kernel<<<1, 64>>>();
    conv1_kernel<<<nblk, 256>>>(x, nidx, nmask, W1, N, K);
    finalize_kernel<<<1, 64>>>(gamma, beta, 1.0f / (float)N);
    mlp_kernel<<<nblk, 256, smem3>>>(x, W2, W3, out, N);
}

// round 3
// speedup vs baseline: 1.7111x; 1.7111x over previous
#include <cuda_runtime.h>
#include <cuda_bf16.h>
#include <cstdint>

#define D 64
#define MAXN 150208
#define KMAX 27

// ---- scratch (static device arrays: allocation-free) ----
__device__ float g_out1[(size_t)MAXN * D];   // conv1 output
__device__ float g_sum[D];
__device__ float g_sq[D];
__device__ float g_scale[D];
__device__ float g_shift[D];
// W1 transposed to [k][n_out][c_in], split into bf16 hi/lo
__device__ __nv_bfloat16 g_W1bf_hi[(size_t)KMAX * 4096];
__device__ __nv_bfloat16 g_W1bf_lo[(size_t)KMAX * 4096];

// ============================================================
// helpers
// ============================================================
__device__ __forceinline__ uint32_t smem_u32(const void* p) {
    uint32_t a;
    asm("{ .reg .u64 t; cvta.to.shared.u64 t, %1; cvt.u32.u64 %0, t; }" : "=r"(a) : "l"(p));
    return a;
}

__device__ __forceinline__ void ldm_x4(uint32_t* r, uint32_t addr) {
    asm volatile("ldmatrix.sync.aligned.m8n8.x4.shared.b16 {%0,%1,%2,%3}, [%4];"
                 : "=r"(r[0]), "=r"(r[1]), "=r"(r[2]), "=r"(r[3]) : "r"(addr));
}

__device__ __forceinline__ void mma_bf16(float* d, const uint32_t* a, const uint32_t* b) {
    asm volatile(
        "mma.sync.aligned.m16n8k16.row.col.f32.bf16.bf16.f32 "
        "{%0,%1,%2,%3},{%4,%5,%6,%7},{%8,%9},{%0,%1,%2,%3};"
        : "+f"(d[0]), "+f"(d[1]), "+f"(d[2]), "+f"(d[3])
        : "r"(a[0]), "r"(a[1]), "r"(a[2]), "r"(a[3]), "r"(b[0]), "r"(b[1]));
}

// split two floats into packed bf16 hi / lo pairs
__device__ __forceinline__ void split2(float a, float b, uint32_t& h, uint32_t& l) {
    __nv_bfloat162 hh = __floats2bfloat162_rn(a, b);
    float ra = a - __bfloat162float(hh.x);
    float rb = b - __bfloat162float(hh.y);
    __nv_bfloat162 ll = __floats2bfloat162_rn(ra, rb);
    h = *(uint32_t*)&hh;
    l = *(uint32_t*)&ll;
}

// ============================================================
// small kernels
// ============================================================
__global__ void zero_stats_kernel() {
    int t = threadIdx.x;
    if (t < D) { g_sum[t] = 0.f; g_sq[t] = 0.f; }
}

// W1[k][c][n] -> Wt[k][n][c] bf16 hi/lo
__global__ void prep_w_kernel(const float* __restrict__ W1, int K) {
    int k = blockIdx.x;
    if (k >= K) return;
    const float* Wk = W1 + (size_t)k * 4096;
    __nv_bfloat16* dh = g_W1bf_hi + (size_t)k * 4096;
    __nv_bfloat16* dl = g_W1bf_lo + (size_t)k * 4096;
    for (int e = threadIdx.x; e < 4096; e += blockDim.x) {
        int n = e >> 6, c = e & 63;
        float v = Wk[c * 64 + n];
        __nv_bfloat16 hi = __float2bfloat16_rn(v);
        float lo = v - __bfloat162float(hi);
        dh[n * 64 + c] = hi;
        dl[n * 64 + c] = __float2bfloat16_rn(lo);
    }
}

// ============================================================
// conv1 via mma.sync bf16x3: 128-row x 64-col tile per CTA, 8 warps.
// smem: Ahi[128][72] Alo[128][72] Whi[64][72] Wlo[64][72]  (bf16, padded)
// ============================================================
#define ASTRIDE 72
__global__ __launch_bounds__(256) void conv1_mma_kernel(
    const float* __restrict__ x,
    const int*   __restrict__ nbr_idx,
    const int*   __restrict__ nbr_mask,
    int N, int K)
{
    extern __shared__ __align__(16) __nv_bfloat16 sm[];
    __nv_bfloat16* Ahi = sm;                       // 128*72
    __nv_bfloat16* Alo = Ahi + 128 * ASTRIDE;      // 128*72
    __nv_bfloat16* Whi = Alo + 128 * ASTRIDE;      // 64*72
    __nv_bfloat16* Wlo = Whi + 64 * ASTRIDE;       // 64*72

    const int tid  = threadIdx.x;
    const int wid  = tid >> 5;
    const int lane = tid & 31;
    const int row0 = blockIdx.x * 128;

    // gather assignment: thread -> (row, 32-float half)
    const int gr   = tid >> 1;
    const int half = tid & 1;
    const int grow = row0 + gr;
    char* aH = (char*)(Ahi + gr * ASTRIDE + half * 32);
    char* aL = (char*)(Alo + gr * ASTRIDE + half * 32);

    // mma tile assignment
    const int m0 = (wid & 3) * 32;
    const int n0 = (wid >> 2) * 32;

    // ldmatrix lane base addresses (bytes), before kk offset
    const uint32_t uAhi = smem_u32(Ahi), uAlo = smem_u32(Alo);
    const uint32_t uWhi = smem_u32(Whi), uWlo = smem_u32(Wlo);
    const uint32_t arow = (uint32_t)(m0 + (lane & 15));
    const uint32_t acol = (uint32_t)((lane >> 4) * 8);
    uint32_t aA0 = (arow * ASTRIDE + acol) * 2;            // m-tile 0
    uint32_t aA1 = ((arow + 16) * ASTRIDE + acol) * 2;     // m-tile 1
    const uint32_t brow = (uint32_t)(n0 + (lane & 7) + ((lane >> 4) << 3));
    const uint32_t bcol = (uint32_t)(((lane >> 3) & 1) * 8);
    uint32_t aB0 = (brow * ASTRIDE + bcol) * 2;            // n-tiles 0,1
    uint32_t aB1 = ((brow + 16) * ASTRIDE + bcol) * 2;     // n-tiles 2,3

    float acc[2][4][4];
#pragma unroll
    for (int mt = 0; mt < 2; ++mt)
#pragma unroll
        for (int nt = 0; nt < 4; ++nt)
#pragma unroll
            for (int e = 0; e < 4; ++e) acc[mt][nt][e] = 0.f;

    for (int k = 0; k < K; ++k) {
        // ---- W tile copy (global [n][64] -> smem [n][72]) ----
        {
            const uint4* sh = (const uint4*)(g_W1bf_hi + (size_t)k * 4096);
            const uint4* sl = (const uint4*)(g_W1bf_lo + (size_t)k * 4096);
#pragma unroll
            for (int i = 0; i < 2; ++i) {
                int f = tid + i * 256;        // 0..511 : row = f>>3, chunk = f&7
                int r = f >> 3, c8 = f & 7;
                *(uint4*)((char*)(Whi + r * ASTRIDE) + c8 * 16) = sh[f];
                *(uint4*)((char*)(Wlo + r * ASTRIDE) + c8 * 16) = sl[f];
            }
        }

        // ---- masked gather + bf16 split ----
        int m = 0;
        const float4* src = nullptr;
        if (grow < N) {
            m = nbr_mask[(size_t)k * N + grow];
            if (m) src = (const float4*)(x + (size_t)nbr_idx[(size_t)k * N + grow] * D + half * 32);
        }
        if (m) {
#pragma unroll
            for (int j = 0; j < 4; ++j) {
                float4 v0 = src[2 * j], v1 = src[2 * j + 1];
                uint4 h, l;
                split2(v0.x, v0.y, h.x, l.x);
                split2(v0.z, v0.w, h.y, l.y);
                split2(v1.x, v1.y, h.z, l.z);
                split2(v1.z, v1.w, h.w, l.w);
                *(uint4*)(aH + j * 16) = h;
                *(uint4*)(aL + j * 16) = l;
            }
        } else {
            const uint4 z = make_uint4(0, 0, 0, 0);
#pragma unroll
            for (int j = 0; j < 4; ++j) {
                *(uint4*)(aH + j * 16) = z;
                *(uint4*)(aL + j * 16) = z;
            }
        }
        __syncthreads();

        // ---- mma: acc += Ahi*Whi + Alo*Whi + Ahi*Wlo ----
#pragma unroll
        for (int kk = 0; kk < 4; ++kk) {
            const uint32_t ko = kk * 32;   // 16 bf16 = 32 bytes
            uint32_t ah[8], al[8], bh[8], bl[8];
            ldm_x4(ah,     uAhi + aA0 + ko);
            ldm_x4(ah + 4, uAhi + aA1 + ko);
            ldm_x4(al,     uAlo + aA0 + ko);
            ldm_x4(al + 4, uAlo + aA1 + ko);
            ldm_x4(bh,     uWhi + aB0 + ko);
            ldm_x4(bh + 4, uWhi + aB1 + ko);
            ldm_x4(bl,     uWlo + aB0 + ko);
            ldm_x4(bl + 4, uWlo + aB1 + ko);
#pragma unroll
            for (int mt = 0; mt < 2; ++mt) {
#pragma unroll
                for (int nt = 0; nt < 4; ++nt) {
                    mma_bf16(acc[mt][nt], ah + mt * 4, bh + nt * 2);
                    mma_bf16(acc[mt][nt], al + mt * 4, bh + nt * 2);
                    mma_bf16(acc[mt][nt], ah + mt * 4, bl + nt * 2);
                }
            }
        }
        __syncthreads();
    }

    // ---- epilogue: write accumulators ----
#pragma unroll
    for (int mt = 0; mt < 2; ++mt) {
        int r0 = row0 + m0 + mt * 16 + (lane >> 2);
        int r1 = r0 + 8;
        int cb = n0 + (lane & 3) * 2;
        if (r0 < N) {
            float* o = g_out1 + (size_t)r0 * D + cb;
#pragma unroll
            for (int nt = 0; nt < 4; ++nt) {
                o[nt * 8 + 0] = acc[mt][nt][0];
                o[nt * 8 + 1] = acc[mt][nt][1];
            }
        }
        if (r1 < N) {
            float* o = g_out1 + (size_t)r1 * D + cb;
#pragma unroll
            for (int nt = 0; nt < 4; ++nt) {
                o[nt * 8 + 0] = acc[mt][nt][2];
                o[nt * 8 + 1] = acc[mt][nt][3];
            }
        }
    }
}

// ============================================================
// per-channel BN stats over g_out1 (L2-resident)
// ============================================================
__global__ __launch_bounds__(256) void stats_kernel(int N) {
    __shared__ float ss[D], sq[D];
    const int tid = threadIdx.x;
    if (tid < D) { ss[tid] = 0.f; sq[tid] = 0.f; }
    __syncthreads();

    const int c4 = (tid & 15) * 4;
    float s0 = 0, s1 = 0, s2 = 0, s3 = 0;
    float q0 = 0, q1 = 0, q2 = 0, q3 = 0;
    for (int rr = blockIdx.x * 16 + (tid >> 4); rr < N; rr += gridDim.x * 16) {
        float4 v = *(const float4*)(g_out1 + (size_t)rr * D + c4);
        s0 += v.x; q0 += v.x * v.x;
        s1 += v.y; q1 += v.y * v.y;
        s2 += v.z; q2 += v.z * v.z;
        s3 += v.w; q3 += v.w * v.w;
    }
    atomicAdd(&ss[c4 + 0], s0); atomicAdd(&sq[c4 + 0], q0);
    atomicAdd(&ss[c4 + 1], s1); atomicAdd(&sq[c4 + 1], q1);
    atomicAdd(&ss[c4 + 2], s2); atomicAdd(&sq[c4 + 2], q2);
    atomicAdd(&ss[c4 + 3], s3); atomicAdd(&sq[c4 + 3], q3);
    __syncthreads();
    if (tid < D) {
        atomicAdd(&g_sum[tid], ss[tid]);
        atomicAdd(&g_sq [tid], sq[tid]);
    }
}

__global__ void finalize_kernel(const float* __restrict__ gamma,
                                const float* __restrict__ beta,
                                float invN)
{
    int c = threadIdx.x;
    if (c < D) {
        float mean = g_sum[c] * invN;
        float var  = g_sq[c] * invN - mean * mean;
        float rstd = rsqrtf(var + 1e-5f);
        float sc   = rstd * gamma[c];
        g_scale[c] = sc;
        g_shift[c] = beta[c] - mean * sc;
    }
}

// ============================================================
// fused MLP: h = BN(out1); out = relu(h @ W2) @ W3 + x
// ============================================================
__global__ __launch_bounds__(256) void mlp_kernel(
    const float* __restrict__ x,
    const float* __restrict__ W2,
    const float* __restrict__ W3,
    float* __restrict__ out,
    int N)
{
    extern __shared__ __align__(16) float smem[];
    float* Hs  = smem;
    float* Tc  = Hs  + 64 * 68;
    float* Wb2 = Tc  + 64 * 68;
    float* Wb3 = Wb2 + 64 * 64;
    float* sc  = Wb3 + 64 * 64;
    float* sh  = sc + 64;

    const int tid = threadIdx.x;
    const int tx  = tid & 15;
    const int ty  = tid >> 4;
    const int row0 = blockIdx.x * 64;

    if (tid < D) { sc[tid] = g_scale[tid]; sh[tid] = g_shift[tid]; }
    __syncthreads();

    {
        int r  = tid >> 2;
        int c0 = (tid & 3) * 16;
        int row = row0 + r;
#pragma unroll
        for (int t = 0; t < 16; ++t) {
            int c = c0 + t;
            float v = (row < N) ? g_out1[(size_t)row * D + c] : 0.f;
            Hs[r * 68 + c] = v * sc[c] + sh[c];
        }
    }

    float acc2[4][4];
#pragma unroll
    for (int i = 0; i < 4; ++i)
#pragma unroll
        for (int ii = 0; ii < 4; ++ii) acc2[i][ii] = 0.f;

    for (int cb = 0; cb < 4; ++cb) {
        const int c0 = cb * 64;

#pragma unroll
        for (int t = 0; t < 4; ++t) {
            int f  = tid + t * 256;
            int j  = f >> 4;
            int c4 = (f & 15) << 2;
            *(float4*)(Wb2 + j * 64 + c4) =
                *(const float4*)(W2 + (size_t)j * 256 + c0 + c4);
        }
        __syncthreads();

        float acc1[4][4];
#pragma unroll
        for (int i = 0; i < 4; ++i)
#pragma unroll
            for (int ii = 0; ii < 4; ++ii) acc1[i][ii] = 0.f;

#pragma unroll 16
        for (int j = 0; j < 64; ++j) {
            float4 b = *(const float4*)(Wb2 + j * 64 + tx * 4);
#pragma unroll
            for (int i = 0; i < 4; ++i) {
                float a = Hs[(ty * 4 + i) * 68 + j];
                acc1[i][0] += a * b.x;
                acc1[i][1] += a * b.y;
                acc1[i][2] += a * b.z;
                acc1[i][3] += a * b.w;
            }
        }

#pragma unroll
        for (int i = 0; i < 4; ++i) {
            float4 v = make_float4(fmaxf(acc1[i][0], 0.f), fmaxf(acc1[i][1], 0.f),
                                   fmaxf(acc1[i][2], 0.f), fmaxf(acc1[i][3], 0.f));
            *(float4*)(Tc + (ty * 4 + i) * 68 + tx * 4) = v;
        }

#pragma unroll
        for (int t = 0; t < 4; ++t) {
            int f = tid + t * 256;
            ((float4*)Wb3)[f] = ((const float4*)(W3 + (size_t)c0 * 64))[f];
        }
        __syncthreads();

#pragma unroll 16
        for (int j = 0; j < 64; ++j) {
            float4 b = *(const float4*)(Wb3 + j * 64 + tx * 4);
#pragma unroll
            for (int i = 0; i < 4; ++i) {
                float a = Tc[(ty * 4 + i) * 68 + j];
                acc2[i][0] += a * b.x;
                acc2[i][1] += a * b.y;
                acc2[i][2] += a * b.z;
                acc2[i][3] += a * b.w;
            }
        }
        __syncthreads();
    }

#pragma unroll
    for (int i = 0; i < 4; ++i) {
        int row = row0 + ty * 4 + i;
        if (row < N) {
            float4 xv = *(const float4*)(x + (size_t)row * D + tx * 4);
            float4 o  = make_float4(acc2[i][0] + xv.x, acc2[i][1] + xv.y,
                                    acc2[i][2] + xv.z, acc2[i][3] + xv.w);
            *(float4*)(out + (size_t)row * D + tx * 4) = o;
        }
    }
}

// ============================================================
// launch
// ============================================================
extern "C" void kernel_launch(void* const* d_in, const int* in_sizes, int n_in,
                              void* d_out, int out_size)
{
    const float* x     = (const float*)d_in[0];
    const int*   nidx  = (const int*)  d_in[1];
    const int*   nmask = (const int*)  d_in[2];
    const float* W1    = (const float*)d_in[3];
    const float* gamma = (const float*)d_in[4];
    const float* beta  = (const float*)d_in[5];
    const float* W2    = (const float*)d_in[6];
    const float* W3    = (const float*)d_in[7];
    float* out = (float*)d_out;

    const int N = in_sizes[0] / D;
    const int K = in_sizes[1] / N;

    const int conv_smem = (128 * ASTRIDE * 2 + 64 * ASTRIDE * 2) * 2;  // bytes
    cudaFuncSetAttribute(conv1_mma_kernel, cudaFuncAttributeMaxDynamicSharedMemorySize, conv_smem);
    const int mlp_smem = (64 * 68 * 2 + 64 * 64 * 2 + 128) * (int)sizeof(float);
    cudaFuncSetAttribute(mlp_kernel, cudaFuncAttributeMaxDynamicSharedMemorySize, mlp_smem);

    prep_w_kernel<<<K, 256>>>(W1, K);
    zero_stats_kernel<<<1, 64>>>();
    conv1_mma_kernel<<<(N + 127) / 128, 256, conv_smem>>>(x, nidx, nmask, N, K);
    stats_kernel<<<296, 256>>>(N);
    finalize_kernel<<<1, 64>>>(gamma, beta, 1.0f / (float)N);
    mlp_kernel<<<(N + 63) / 64, 256, mlp_smem>>>(x, W2, W3, out, N);
}

// round 4
// speedup vs baseline: 2.2488x; 1.3142x over previous
#include <cuda_runtime.h>
#include <cuda_bf16.h>
#include <cstdint>

#define D 64
#define MAXN 150208
#define KMAX 27

// ---- scratch (static device arrays: allocation-free) ----
__device__ float g_out1[(size_t)MAXN * D];   // conv1 output
__device__ float g_sum[D];
__device__ float g_sq[D];
__device__ float g_scale[D];
__device__ float g_shift[D];
// W1 transposed to [k][n_out][c_in], split into bf16 hi/lo
__device__ __nv_bfloat16 g_W1bf_hi[(size_t)KMAX * 4096];
__device__ __nv_bfloat16 g_W1bf_lo[(size_t)KMAX * 4096];
// W2^T [256][64], W3^T [64][256] split into bf16 hi/lo
__device__ __nv_bfloat16 g_W2bf_hi[256 * 64];
__device__ __nv_bfloat16 g_W2bf_lo[256 * 64];
__device__ __nv_bfloat16 g_W3bf_hi[64 * 256];
__device__ __nv_bfloat16 g_W3bf_lo[64 * 256];

// ============================================================
// helpers
// ============================================================
__device__ __forceinline__ uint32_t smem_u32(const void* p) {
    uint32_t a;
    asm("{ .reg .u64 t; cvta.to.shared.u64 t, %1; cvt.u32.u64 %0, t; }" : "=r"(a) : "l"(p));
    return a;
}

__device__ __forceinline__ void ldm_x4(uint32_t* r, uint32_t addr) {
    asm volatile("ldmatrix.sync.aligned.m8n8.x4.shared.b16 {%0,%1,%2,%3}, [%4];"
                 : "=r"(r[0]), "=r"(r[1]), "=r"(r[2]), "=r"(r[3]) : "r"(addr));
}

__device__ __forceinline__ void mma_bf16(float* d, const uint32_t* a, const uint32_t* b) {
    asm volatile(
        "mma.sync.aligned.m16n8k16.row.col.f32.bf16.bf16.f32 "
        "{%0,%1,%2,%3},{%4,%5,%6,%7},{%8,%9},{%0,%1,%2,%3};"
        : "+f"(d[0]), "+f"(d[1]), "+f"(d[2]), "+f"(d[3])
        : "r"(a[0]), "r"(a[1]), "r"(a[2]), "r"(a[3]), "r"(b[0]), "r"(b[1]));
}

// split two floats into packed bf16 hi / lo pairs
__device__ __forceinline__ void split2(float a, float b, uint32_t& h, uint32_t& l) {
    __nv_bfloat162 hh = __floats2bfloat162_rn(a, b);
    float ra = a - __bfloat162float(hh.x);
    float rb = b - __bfloat162float(hh.y);
    __nv_bfloat162 ll = __floats2bfloat162_rn(ra, rb);
    h = *(uint32_t*)&hh;
    l = *(uint32_t*)&ll;
}

// ============================================================
// small kernels
// ============================================================
__global__ void zero_stats_kernel() {
    int t = threadIdx.x;
    if (t < D) { g_sum[t] = 0.f; g_sq[t] = 0.f; }
}

// W1[k][c][n] -> Wt[k][n][c] bf16 hi/lo
__global__ void prep_w_kernel(const float* __restrict__ W1, int K) {
    int k = blockIdx.x;
    if (k >= K) return;
    const float* Wk = W1 + (size_t)k * 4096;
    __nv_bfloat16* dh = g_W1bf_hi + (size_t)k * 4096;
    __nv_bfloat16* dl = g_W1bf_lo + (size_t)k * 4096;
    for (int e = threadIdx.x; e < 4096; e += blockDim.x) {
        int n = e >> 6, c = e & 63;
        float v = Wk[c * 64 + n];
        __nv_bfloat16 hi = __float2bfloat16_rn(v);
        float lo = v - __bfloat162float(hi);
        dh[n * 64 + c] = hi;
        dl[n * 64 + c] = __float2bfloat16_rn(lo);
    }
}

// W2 [64][256] -> W2t [n][c]; W3 [256][64] -> W3t [n][c]
__global__ void prep_w23_kernel(const float* __restrict__ W2,
                                const float* __restrict__ W3) {
    int e = blockIdx.x * blockDim.x + threadIdx.x;
    if (e < 256 * 64) {
        int n = e >> 6, c = e & 63;   // W2t[n][c] = W2[c][n]
        float v = W2[(size_t)c * 256 + n];
        __nv_bfloat16 hi = __float2bfloat16_rn(v);
        float lo = v - __bfloat162float(hi);
        g_W2bf_hi[n * 64 + c] = hi;
        g_W2bf_lo[n * 64 + c] = __float2bfloat16_rn(lo);
    }
    if (e < 64 * 256) {
        int n = e >> 8, c = e & 255;  // W3t[n][c] = W3[c][n]
        float v = W3[(size_t)c * 64 + n];
        __nv_bfloat16 hi = __float2bfloat16_rn(v);
        float lo = v - __bfloat162float(hi);
        g_W3bf_hi[n * 256 + c] = hi;
        g_W3bf_lo[n * 256 + c] = __float2bfloat16_rn(lo);
    }
}

// ============================================================
// conv1 via mma.sync bf16x3: 128x64 tile per CTA, 8 warps.
// Also accumulates per-channel BN stats (pad rows are exact zeros).
// ============================================================
#define ASTRIDE 72
__global__ __launch_bounds__(256) void conv1_mma_kernel(
    const float* __restrict__ x,
    const int*   __restrict__ nbr_idx,
    const int*   __restrict__ nbr_mask,
    int N, int K)
{
    extern __shared__ __align__(16) __nv_bfloat16 sm[];
    __nv_bfloat16* Ahi = sm;                       // 128*72
    __nv_bfloat16* Alo = Ahi + 128 * ASTRIDE;      // 128*72
    __nv_bfloat16* Whi = Alo + 128 * ASTRIDE;      // 64*72
    __nv_bfloat16* Wlo = Whi + 64 * ASTRIDE;       // 64*72
    __shared__ float s_sum[D], s_sq[D];

    const int tid  = threadIdx.x;
    const int wid  = tid >> 5;
    const int lane = tid & 31;
    const int row0 = blockIdx.x * 128;

    if (tid < D) { s_sum[tid] = 0.f; s_sq[tid] = 0.f; }

    const int gr   = tid >> 1;
    const int half = tid & 1;
    const int grow = row0 + gr;
    char* aH = (char*)(Ahi + gr * ASTRIDE + half * 32);
    char* aL = (char*)(Alo + gr * ASTRIDE + half * 32);

    const int m0 = (wid & 3) * 32;
    const int n0 = (wid >> 2) * 32;

    const uint32_t uAhi = smem_u32(Ahi), uAlo = smem_u32(Alo);
    const uint32_t uWhi = smem_u32(Whi), uWlo = smem_u32(Wlo);
    const uint32_t arow = (uint32_t)(m0 + (lane & 15));
    const uint32_t acol = (uint32_t)((lane >> 4) * 8);
    uint32_t aA0 = (arow * ASTRIDE + acol) * 2;
    uint32_t aA1 = ((arow + 16) * ASTRIDE + acol) * 2;
    const uint32_t brow = (uint32_t)(n0 + (lane & 7) + ((lane >> 4) << 3));
    const uint32_t bcol = (uint32_t)(((lane >> 3) & 1) * 8);
    uint32_t aB0 = (brow * ASTRIDE + bcol) * 2;
    uint32_t aB1 = ((brow + 16) * ASTRIDE + bcol) * 2;

    float acc[2][4][4];
#pragma unroll
    for (int mt = 0; mt < 2; ++mt)
#pragma unroll
        for (int nt = 0; nt < 4; ++nt)
#pragma unroll
            for (int e = 0; e < 4; ++e) acc[mt][nt][e] = 0.f;

    for (int k = 0; k < K; ++k) {
        {
            const uint4* sh = (const uint4*)(g_W1bf_hi + (size_t)k * 4096);
            const uint4* sl = (const uint4*)(g_W1bf_lo + (size_t)k * 4096);
#pragma unroll
            for (int i = 0; i < 2; ++i) {
                int f = tid + i * 256;
                int r = f >> 3, c8 = f & 7;
                *(uint4*)((char*)(Whi + r * ASTRIDE) + c8 * 16) = sh[f];
                *(uint4*)((char*)(Wlo + r * ASTRIDE) + c8 * 16) = sl[f];
            }
        }

        int m = 0;
        const float4* src = nullptr;
        if (grow < N) {
            m = nbr_mask[(size_t)k * N + grow];
            if (m) src = (const float4*)(x + (size_t)nbr_idx[(size_t)k * N + grow] * D + half * 32);
        }
        if (m) {
#pragma unroll
            for (int j = 0; j < 4; ++j) {
                float4 v0 = src[2 * j], v1 = src[2 * j + 1];
                uint4 h, l;
                split2(v0.x, v0.y, h.x, l.x);
                split2(v0.z, v0.w, h.y, l.y);
                split2(v1.x, v1.y, h.z, l.z);
                split2(v1.z, v1.w, h.w, l.w);
                *(uint4*)(aH + j * 16) = h;
                *(uint4*)(aL + j * 16) = l;
            }
        } else {
            const uint4 z = make_uint4(0, 0, 0, 0);
#pragma unroll
            for (int j = 0; j < 4; ++j) {
                *(uint4*)(aH + j * 16) = z;
                *(uint4*)(aL + j * 16) = z;
            }
        }
        __syncthreads();

#pragma unroll
        for (int kk = 0; kk < 4; ++kk) {
            const uint32_t ko = kk * 32;
            uint32_t ah[8], al[8], bh[8], bl[8];
            ldm_x4(ah,     uAhi + aA0 + ko);
            ldm_x4(ah + 4, uAhi + aA1 + ko);
            ldm_x4(al,     uAlo + aA0 + ko);
            ldm_x4(al + 4, uAlo + aA1 + ko);
            ldm_x4(bh,     uWhi + aB0 + ko);
            ldm_x4(bh + 4, uWhi + aB1 + ko);
            ldm_x4(bl,     uWlo + aB0 + ko);
            ldm_x4(bl + 4, uWlo + aB1 + ko);
#pragma unroll
            for (int mt = 0; mt < 2; ++mt) {
#pragma unroll
                for (int nt = 0; nt < 4; ++nt) {
                    mma_bf16(acc[mt][nt], ah + mt * 4, bh + nt * 2);
                    mma_bf16(acc[mt][nt], al + mt * 4, bh + nt * 2);
                    mma_bf16(acc[mt][nt], ah + mt * 4, bl + nt * 2);
                }
            }
        }
        __syncthreads();
    }

    // ---- epilogue: store + BN-stat accumulation ----
#pragma unroll
    for (int mt = 0; mt < 2; ++mt) {
        int r0 = row0 + m0 + mt * 16 + (lane >> 2);
        int r1 = r0 + 8;
        int cb = n0 + (lane & 3) * 2;
        if (r0 < N) {
            float* o = g_out1 + (size_t)r0 * D + cb;
#pragma unroll
            for (int nt = 0; nt < 4; ++nt) {
                o[nt * 8 + 0] = acc[mt][nt][0];
                o[nt * 8 + 1] = acc[mt][nt][1];
            }
        }
        if (r1 < N) {
            float* o = g_out1 + (size_t)r1 * D + cb;
#pragma unroll
            for (int nt = 0; nt < 4; ++nt) {
                o[nt * 8 + 0] = acc[mt][nt][2];
                o[nt * 8 + 1] = acc[mt][nt][3];
            }
        }
    }
    // per-column stats: pad rows hold exact zeros -> safe unmasked
    {
        int cb = n0 + (lane & 3) * 2;
#pragma unroll
        for (int nt = 0; nt < 4; ++nt) {
            float cs0 = 0.f, cq0 = 0.f, cs1 = 0.f, cq1 = 0.f;
#pragma unroll
            for (int mt = 0; mt < 2; ++mt) {
                float a0 = acc[mt][nt][0], a2 = acc[mt][nt][2];
                float a1 = acc[mt][nt][1], a3 = acc[mt][nt][3];
                cs0 += a0 + a2; cq0 += a0 * a0 + a2 * a2;
                cs1 += a1 + a3; cq1 += a1 * a1 + a3 * a3;
            }
            atomicAdd(&s_sum[cb + nt * 8 + 0], cs0);
            atomicAdd(&s_sq [cb + nt * 8 + 0], cq0);
            atomicAdd(&s_sum[cb + nt * 8 + 1], cs1);
            atomicAdd(&s_sq [cb + nt * 8 + 1], cq1);
        }
    }
    __syncthreads();
    if (tid < D) {
        atomicAdd(&g_sum[tid], s_sum[tid]);
        atomicAdd(&g_sq [tid], s_sq[tid]);
    }
}

__global__ void finalize_kernel(const float* __restrict__ gamma,
                                const float* __restrict__ beta,
                                float invN)
{
    int c = threadIdx.x;
    if (c < D) {
        float mean = g_sum[c] * invN;
        float var  = g_sq[c] * invN - mean * mean;
        float rstd = rsqrtf(var + 1e-5f);
        float sc   = rstd * gamma[c];
        g_scale[c] = sc;
        g_shift[c] = beta[c] - mean * sc;
    }
}

// ============================================================
// fused MLP via mma.sync bf16x3: 128-row tile per CTA, 8 warps.
// h = BN(out1); out = relu(h @ W2) @ W3 + x
// smem: Ahi/Alo[128][72], Thi/Tlo[128][72], Whi/Wlo[64][72] (reused W2/W3)
// ============================================================
__global__ __launch_bounds__(256) void mlp_mma_kernel(
    const float* __restrict__ x,
    float* __restrict__ out,
    int N)
{
    extern __shared__ __align__(16) __nv_bfloat16 sm[];
    __nv_bfloat16* Ahi = sm;
    __nv_bfloat16* Alo = Ahi + 128 * ASTRIDE;
    __nv_bfloat16* Thi = Alo + 128 * ASTRIDE;
    __nv_bfloat16* Tlo = Thi + 128 * ASTRIDE;
    __nv_bfloat16* Whi = Tlo + 128 * ASTRIDE;
    __nv_bfloat16* Wlo = Whi + 64 * ASTRIDE;
    __shared__ float s_sc[D], s_sh[D];

    const int tid  = threadIdx.x;
    const int wid  = tid >> 5;
    const int lane = tid & 31;
    const int row0 = blockIdx.x * 128;

    if (tid < D) { s_sc[tid] = g_scale[tid]; s_sh[tid] = g_shift[tid]; }
    __syncthreads();

    // ---- build A = BN(out1 tile), bf16 split ----
    {
        const int r    = tid >> 1;
        const int half = tid & 1;
        const int row  = row0 + r;
        char* aH = (char*)(Ahi + r * ASTRIDE + half * 32);
        char* aL = (char*)(Alo + r * ASTRIDE + half * 32);
        if (row < N) {
            const float4* src = (const float4*)(g_out1 + (size_t)row * D + half * 32);
            const int cb = half * 32;
#pragma unroll
            for (int j = 0; j < 4; ++j) {
                float4 v0 = src[2 * j], v1 = src[2 * j + 1];
                int c = cb + j * 8;
                v0.x = v0.x * s_sc[c + 0] + s_sh[c + 0];
                v0.y = v0.y * s_sc[c + 1] + s_sh[c + 1];
                v0.z = v0.z * s_sc[c + 2] + s_sh[c + 2];
                v0.w = v0.w * s_sc[c + 3] + s_sh[c + 3];
                v1.x = v1.x * s_sc[c + 4] + s_sh[c + 4];
                v1.y = v1.y * s_sc[c + 5] + s_sh[c + 5];
                v1.z = v1.z * s_sc[c + 6] + s_sh[c + 6];
                v1.w = v1.w * s_sc[c + 7] + s_sh[c + 7];
                uint4 h, l;
                split2(v0.x, v0.y, h.x, l.x);
                split2(v0.z, v0.w, h.y, l.y);
                split2(v1.x, v1.y, h.z, l.z);
                split2(v1.z, v1.w, h.w, l.w);
                *(uint4*)(aH + j * 16) = h;
                *(uint4*)(aL + j * 16) = l;
            }
        } else {
            const uint4 z = make_uint4(0, 0, 0, 0);
#pragma unroll
            for (int j = 0; j < 4; ++j) {
                *(uint4*)(aH + j * 16) = z;
                *(uint4*)(aL + j * 16) = z;
            }
        }
    }

    const int m0 = (wid & 3) * 32;
    const int n0 = (wid >> 2) * 32;

    const uint32_t uAhi = smem_u32(Ahi), uAlo = smem_u32(Alo);
    const uint32_t uThi = smem_u32(Thi), uTlo = smem_u32(Tlo);
    const uint32_t uWhi = smem_u32(Whi), uWlo = smem_u32(Wlo);
    const uint32_t arow = (uint32_t)(m0 + (lane & 15));
    const uint32_t acol = (uint32_t)((lane >> 4) * 8);
    const uint32_t aA0 = (arow * ASTRIDE + acol) * 2;
    const uint32_t aA1 = ((arow + 16) * ASTRIDE + acol) * 2;
    const uint32_t brow = (uint32_t)(n0 + (lane & 7) + ((lane >> 4) << 3));
    const uint32_t bcol = (uint32_t)(((lane >> 3) & 1) * 8);
    const uint32_t aB0 = (brow * ASTRIDE + bcol) * 2;
    const uint32_t aB1 = ((brow + 16) * ASTRIDE + bcol) * 2;

    float acc2[2][4][4];
#pragma unroll
    for (int mt = 0; mt < 2; ++mt)
#pragma unroll
        for (int nt = 0; nt < 4; ++nt)
#pragma unroll
            for (int e = 0; e < 4; ++e) acc2[mt][nt][e] = 0.f;

    for (int cb4 = 0; cb4 < 4; ++cb4) {
        const int c0 = cb4 * 64;

        // ---- load W2 chunk: rows n (out col c0+n), 64 bf16 contiguous ----
        {
            const uint4* sh = (const uint4*)(g_W2bf_hi + (size_t)c0 * 64);
            const uint4* sl = (const uint4*)(g_W2bf_lo + (size_t)c0 * 64);
#pragma unroll
            for (int i = 0; i < 2; ++i) {
                int f = tid + i * 256;
                int r = f >> 3, c8 = f & 7;
                *(uint4*)((char*)(Whi + r * ASTRIDE) + c8 * 16) = sh[f];
                *(uint4*)((char*)(Wlo + r * ASTRIDE) + c8 * 16) = sl[f];
            }
        }
        __syncthreads();

        // ---- GEMM1 chunk: acc1 = A @ W2c (3-term) ----
        float acc1[2][4][4];
#pragma unroll
        for (int mt = 0; mt < 2; ++mt)
#pragma unroll
            for (int nt = 0; nt < 4; ++nt)
#pragma unroll
                for (int e = 0; e < 4; ++e) acc1[mt][nt][e] = 0.f;

#pragma unroll
        for (int kk = 0; kk < 4; ++kk) {
            const uint32_t ko = kk * 32;
            uint32_t ah[8], al[8], bh[8], bl[8];
            ldm_x4(ah,     uAhi + aA0 + ko);
            ldm_x4(ah + 4, uAhi + aA1 + ko);
            ldm_x4(al,     uAlo + aA0 + ko);
            ldm_x4(al + 4, uAlo + aA1 + ko);
            ldm_x4(bh,     uWhi + aB0 + ko);
            ldm_x4(bh + 4, uWhi + aB1 + ko);
            ldm_x4(bl,     uWlo + aB0 + ko);
            ldm_x4(bl + 4, uWlo + aB1 + ko);
#pragma unroll
            for (int mt = 0; mt < 2; ++mt) {
#pragma unroll
                for (int nt = 0; nt < 4; ++nt) {
                    mma_bf16(acc1[mt][nt], ah + mt * 4, bh + nt * 2);
                    mma_bf16(acc1[mt][nt], al + mt * 4, bh + nt * 2);
                    mma_bf16(acc1[mt][nt], ah + mt * 4, bl + nt * 2);
                }
            }
        }

        // ---- relu + split -> T ----
#pragma unroll
        for (int mt = 0; mt < 2; ++mt) {
            int lr0 = m0 + mt * 16 + (lane >> 2);
            int lr1 = lr0 + 8;
            int cc  = n0 + (lane & 3) * 2;
#pragma unroll
            for (int nt = 0; nt < 4; ++nt) {
                float v0 = fmaxf(acc1[mt][nt][0], 0.f);
                float v1 = fmaxf(acc1[mt][nt][1], 0.f);
                float v2 = fmaxf(acc1[mt][nt][2], 0.f);
                float v3 = fmaxf(acc1[mt][nt][3], 0.f);
                uint32_t h, l;
                split2(v0, v1, h, l);
                *(uint32_t*)((char*)(Thi + lr0 * ASTRIDE + cc + nt * 8)) = h;
                *(uint32_t*)((char*)(Tlo + lr0 * ASTRIDE + cc + nt * 8)) = l;
                split2(v2, v3, h, l);
                *(uint32_t*)((char*)(Thi + lr1 * ASTRIDE + cc + nt * 8)) = h;
                *(uint32_t*)((char*)(Tlo + lr1 * ASTRIDE + cc + nt * 8)) = l;
            }
        }
        __syncthreads();   // T visible; all warps done reading W2 chunk

        // ---- load W3 chunk: rows n (out col), k slice c0..c0+63 ----
        {
#pragma unroll
            for (int i = 0; i < 2; ++i) {
                int f = tid + i * 256;
                int r = f >> 3, c8 = f & 7;
                *(uint4*)((char*)(Whi + r * ASTRIDE) + c8 * 16) =
                    *((const uint4*)(g_W3bf_hi + (size_t)r * 256 + c0) + c8);
                *(uint4*)((char*)(Wlo + r * ASTRIDE) + c8 * 16) =
                    *((const uint4*)(g_W3bf_lo + (size_t)r * 256 + c0) + c8);
            }
        }
        __syncthreads();

        // ---- GEMM2 chunk: acc2 += T @ W3c (3-term) ----
#pragma unroll
        for (int kk = 0; kk < 4; ++kk) {
            const uint32_t ko = kk * 32;
            uint32_t ah[8], al[8], bh[8], bl[8];
            ldm_x4(ah,     uThi + aA0 + ko);
            ldm_x4(ah + 4, uThi + aA1 + ko);
            ldm_x4(al,     uTlo + aA0 + ko);
            ldm_x4(al + 4, uTlo + aA1 + ko);
            ldm_x4(bh,     uWhi + aB0 + ko);
            ldm_x4(bh + 4, uWhi + aB1 + ko);
            ldm_x4(bl,     uWlo + aB0 + ko);
            ldm_x4(bl + 4, uWlo + aB1 + ko);
#pragma unroll
            for (int mt = 0; mt < 2; ++mt) {
#pragma unroll
                for (int nt = 0; nt < 4; ++nt) {
                    mma_bf16(acc2[mt][nt], ah + mt * 4, bh + nt * 2);
                    mma_bf16(acc2[mt][nt], al + mt * 4, bh + nt * 2);
                    mma_bf16(acc2[mt][nt], ah + mt * 4, bl + nt * 2);
                }
            }
        }
        __syncthreads();   // done with W3 chunk + T before next chunk
    }

    // ---- epilogue: residual + store ----
#pragma unroll
    for (int mt = 0; mt < 2; ++mt) {
        int r0 = row0 + m0 + mt * 16 + (lane >> 2);
        int r1 = r0 + 8;
        int cb = n0 + (lane & 3) * 2;
        if (r0 < N) {
            float* o = out + (size_t)r0 * D + cb;
            const float* xr = x + (size_t)r0 * D + cb;
#pragma unroll
            for (int nt = 0; nt < 4; ++nt) {
                float2 xv = *(const float2*)(xr + nt * 8);
                float2 ov = make_float2(acc2[mt][nt][0] + xv.x, acc2[mt][nt][1] + xv.y);
                *(float2*)(o + nt * 8) = ov;
            }
        }
        if (r1 < N) {
            float* o = out + (size_t)r1 * D + cb;
            const float* xr = x + (size_t)r1 * D + cb;
#pragma unroll
            for (int nt = 0; nt < 4; ++nt) {
                float2 xv = *(const float2*)(xr + nt * 8);
                float2 ov = make_float2(acc2[mt][nt][2] + xv.x, acc2[mt][nt][3] + xv.y);
                *(float2*)(o + nt * 8) = ov;
            }
        }
    }
}

// ============================================================
// launch
// ============================================================
extern "C" void kernel_launch(void* const* d_in, const int* in_sizes, int n_in,
                              void* d_out, int out_size)
{
    const float* x     = (const float*)d_in[0];
    const int*   nidx  = (const int*)  d_in[1];
    const int*   nmask = (const int*)  d_in[2];
    const float* W1    = (const float*)d_in[3];
    const float* gamma = (const float*)d_in[4];
    const float* beta  = (const float*)d_in[5];
    const float* W2    = (const float*)d_in[6];
    const float* W3    = (const float*)d_in[7];
    float* out = (float*)d_out;

    const int N = in_sizes[0] / D;
    const int K = in_sizes[1] / N;
    const int nblk = (N + 127) / 128;

    const int conv_smem = (128 * ASTRIDE * 2 + 64 * ASTRIDE * 2) * 2;
    cudaFuncSetAttribute(conv1_mma_kernel, cudaFuncAttributeMaxDynamicSharedMemorySize, conv_smem);
    const int mlp_smem = (128 * ASTRIDE * 4 + 64 * ASTRIDE * 2) * 2;
    cudaFuncSetAttribute(mlp_mma_kernel, cudaFuncAttributeMaxDynamicSharedMemorySize, mlp_smem);

    prep_w_kernel<<<K, 256>>>(W1, K);
    prep_w23_kernel<<<64, 256>>>(W2, W3);
    zero_stats_kernel<<<1, 64>>>();
    conv1_mma_kernel<<<nblk, 256, conv_smem>>>(x, nidx, nmask, N, K);
    finalize_kernel<<<1, 64>>>(gamma, beta, 1.0f / (float)N);
    mlp_mma_kernel<<<nblk, 256, mlp_smem>>>(x, out, N);
}

// round 5
// speedup vs baseline: 2.5496x; 1.1338x over previous
#include <cuda_runtime.h>
#include <cuda_bf16.h>
#include <cstdint>

#define D 64
#define MAXN 150208
#define KMAX 27

// ---- scratch (static device arrays: allocation-free) ----
__device__ float g_out1[(size_t)MAXN * D];   // conv1 output
__device__ float g_sum[D];
__device__ float g_sq[D];
__device__ float g_scale[D];
__device__ float g_shift[D];
// W1 transposed to [k][n_out][c_in], split into bf16 hi/lo
__device__ __nv_bfloat16 g_W1bf_hi[(size_t)KMAX * 4096];
__device__ __nv_bfloat16 g_W1bf_lo[(size_t)KMAX * 4096];
// W2^T [256][64], W3^T [64][256] split into bf16 hi/lo
__device__ __nv_bfloat16 g_W2bf_hi[256 * 64];
__device__ __nv_bfloat16 g_W2bf_lo[256 * 64];
__device__ __nv_bfloat16 g_W3bf_hi[64 * 256];
__device__ __nv_bfloat16 g_W3bf_lo[64 * 256];

// ============================================================
// helpers
// ============================================================
__device__ __forceinline__ uint32_t smem_u32(const void* p) {
    uint32_t a;
    asm("{ .reg .u64 t; cvta.to.shared.u64 t, %1; cvt.u32.u64 %0, t; }" : "=r"(a) : "l"(p));
    return a;
}

__device__ __forceinline__ void ldm_x4(uint32_t* r, uint32_t addr) {
    asm volatile("ldmatrix.sync.aligned.m8n8.x4.shared.b16 {%0,%1,%2,%3}, [%4];"
                 : "=r"(r[0]), "=r"(r[1]), "=r"(r[2]), "=r"(r[3]) : "r"(addr));
}

__device__ __forceinline__ void mma_bf16(float* d, const uint32_t* a, const uint32_t* b) {
    asm volatile(
        "mma.sync.aligned.m16n8k16.row.col.f32.bf16.bf16.f32 "
        "{%0,%1,%2,%3},{%4,%5,%6,%7},{%8,%9},{%0,%1,%2,%3};"
        : "+f"(d[0]), "+f"(d[1]), "+f"(d[2]), "+f"(d[3])
        : "r"(a[0]), "r"(a[1]), "r"(a[2]), "r"(a[3]), "r"(b[0]), "r"(b[1]));
}

// split two floats into packed bf16 hi / lo pairs
__device__ __forceinline__ void split2(float a, float b, uint32_t& h, uint32_t& l) {
    __nv_bfloat162 hh = __floats2bfloat162_rn(a, b);
    float ra = a - __bfloat162float(hh.x);
    float rb = b - __bfloat162float(hh.y);
    __nv_bfloat162 ll = __floats2bfloat162_rn(ra, rb);
    h = *(uint32_t*)&hh;
    l = *(uint32_t*)&ll;
}

// ============================================================
// small kernels
// ============================================================
__global__ void zero_stats_kernel() {
    int t = threadIdx.x;
    if (t < D) { g_sum[t] = 0.f; g_sq[t] = 0.f; }
}

// W1[k][c][n] -> Wt[k][n][c] bf16 hi/lo
__global__ void prep_w_kernel(const float* __restrict__ W1, int K) {
    int k = blockIdx.x;
    if (k >= K) return;
    const float* Wk = W1 + (size_t)k * 4096;
    __nv_bfloat16* dh = g_W1bf_hi + (size_t)k * 4096;
    __nv_bfloat16* dl = g_W1bf_lo + (size_t)k * 4096;
    for (int e = threadIdx.x; e < 4096; e += blockDim.x) {
        int n = e >> 6, c = e & 63;
        float v = Wk[c * 64 + n];
        __nv_bfloat16 hi = __float2bfloat16_rn(v);
        float lo = v - __bfloat162float(hi);
        dh[n * 64 + c] = hi;
        dl[n * 64 + c] = __float2bfloat16_rn(lo);
    }
}

// W2 [64][256] -> W2t [n][c]; W3 [256][64] -> W3t [n][c]
__global__ void prep_w23_kernel(const float* __restrict__ W2,
                                const float* __restrict__ W3) {
    int e = blockIdx.x * blockDim.x + threadIdx.x;
    if (e < 256 * 64) {
        int n = e >> 6, c = e & 63;
        float v = W2[(size_t)c * 256 + n];
        __nv_bfloat16 hi = __float2bfloat16_rn(v);
        float lo = v - __bfloat162float(hi);
        g_W2bf_hi[n * 64 + c] = hi;
        g_W2bf_lo[n * 64 + c] = __float2bfloat16_rn(lo);
    }
    if (e < 64 * 256) {
        int n = e >> 8, c = e & 255;
        float v = W3[(size_t)c * 64 + n];
        __nv_bfloat16 hi = __float2bfloat16_rn(v);
        float lo = v - __bfloat162float(hi);
        g_W3bf_hi[n * 256 + c] = hi;
        g_W3bf_lo[n * 256 + c] = __float2bfloat16_rn(lo);
    }
}

// ============================================================
// conv1 via mma.sync bf16x3: 256x64 tile per CTA, 8 warps,
// warp tile 64x32 (4 m-tiles x 4 n-tiles).
// Also accumulates per-channel BN stats (pad rows are exact zeros).
// ============================================================
#define ASTRIDE 72
__global__ __launch_bounds__(256, 2) void conv1_mma_kernel(
    const float* __restrict__ x,
    const int*   __restrict__ nbr_idx,
    const int*   __restrict__ nbr_mask,
    int N, int K)
{
    extern __shared__ __align__(16) __nv_bfloat16 sm[];
    __nv_bfloat16* Ahi = sm;                       // 256*72
    __nv_bfloat16* Alo = Ahi + 256 * ASTRIDE;      // 256*72
    __nv_bfloat16* Whi = Alo + 256 * ASTRIDE;      // 64*72
    __nv_bfloat16* Wlo = Whi + 64 * ASTRIDE;       // 64*72
    __shared__ float s_sum[D], s_sq[D];

    const int tid  = threadIdx.x;
    const int wid  = tid >> 5;
    const int lane = tid & 31;
    const int row0 = blockIdx.x * 256;

    if (tid < D) { s_sum[tid] = 0.f; s_sq[tid] = 0.f; }

    // gather: 1 thread per row (full 64-float row)
    const int grow = row0 + tid;
    char* aH = (char*)(Ahi + tid * ASTRIDE);
    char* aL = (char*)(Alo + tid * ASTRIDE);

    // warp tiling: 4 m-groups x 2 n-groups
    const int m0 = (wid & 3) * 64;
    const int n0 = (wid >> 2) * 32;

    const uint32_t uAhi = smem_u32(Ahi), uAlo = smem_u32(Alo);
    const uint32_t uWhi = smem_u32(Whi), uWlo = smem_u32(Wlo);
    const uint32_t acol = (uint32_t)((lane >> 4) * 8);
    uint32_t aA[4];
#pragma unroll
    for (int mt = 0; mt < 4; ++mt)
        aA[mt] = (uint32_t)(((m0 + mt * 16 + (lane & 15)) * ASTRIDE + acol) * 2);
    const uint32_t brow = (uint32_t)(n0 + (lane & 7) + ((lane >> 4) << 3));
    const uint32_t bcol = (uint32_t)(((lane >> 3) & 1) * 8);
    const uint32_t aB0 = (brow * ASTRIDE + bcol) * 2;
    const uint32_t aB1 = ((brow + 16) * ASTRIDE + bcol) * 2;

    float acc[4][4][4];
#pragma unroll
    for (int mt = 0; mt < 4; ++mt)
#pragma unroll
        for (int nt = 0; nt < 4; ++nt)
#pragma unroll
            for (int e = 0; e < 4; ++e) acc[mt][nt][e] = 0.f;

    for (int k = 0; k < K; ++k) {
        // ---- W tile (64x64 hi/lo) ----
        {
            const uint4* sh = (const uint4*)(g_W1bf_hi + (size_t)k * 4096);
            const uint4* sl = (const uint4*)(g_W1bf_lo + (size_t)k * 4096);
#pragma unroll
            for (int i = 0; i < 2; ++i) {
                int f = tid + i * 256;
                int r = f >> 3, c8 = f & 7;
                *(uint4*)((char*)(Whi + r * ASTRIDE) + c8 * 16) = sh[f];
                *(uint4*)((char*)(Wlo + r * ASTRIDE) + c8 * 16) = sl[f];
            }
        }

        // ---- masked gather + bf16 split (full row per thread) ----
        int m = 0;
        const float4* src = nullptr;
        if (grow < N) {
            m = nbr_mask[(size_t)k * N + grow];
            if (m) src = (const float4*)(x + (size_t)nbr_idx[(size_t)k * N + grow] * D);
        }
        if (m) {
#pragma unroll
            for (int j = 0; j < 8; ++j) {
                float4 v0 = src[2 * j], v1 = src[2 * j + 1];
                uint4 h, l;
                split2(v0.x, v0.y, h.x, l.x);
                split2(v0.z, v0.w, h.y, l.y);
                split2(v1.x, v1.y, h.z, l.z);
                split2(v1.z, v1.w, h.w, l.w);
                *(uint4*)(aH + j * 16) = h;
                *(uint4*)(aL + j * 16) = l;
            }
        } else {
            const uint4 z = make_uint4(0, 0, 0, 0);
#pragma unroll
            for (int j = 0; j < 8; ++j) {
                *(uint4*)(aH + j * 16) = z;
                *(uint4*)(aL + j * 16) = z;
            }
        }
        __syncthreads();

        // ---- mma: acc += Ahi*Whi + Alo*Whi + Ahi*Wlo ----
#pragma unroll
        for (int kk = 0; kk < 4; ++kk) {
            const uint32_t ko = kk * 32;
            uint32_t bh[8], bl[8];
            ldm_x4(bh,     uWhi + aB0 + ko);
            ldm_x4(bh + 4, uWhi + aB1 + ko);
            ldm_x4(bl,     uWlo + aB0 + ko);
            ldm_x4(bl + 4, uWlo + aB1 + ko);
#pragma unroll
            for (int mt = 0; mt < 4; ++mt) {
                uint32_t ah[4], al[4];
                ldm_x4(ah, uAhi + aA[mt] + ko);
                ldm_x4(al, uAlo + aA[mt] + ko);
#pragma unroll
                for (int nt = 0; nt < 4; ++nt) {
                    mma_bf16(acc[mt][nt], ah, bh + nt * 2);
                    mma_bf16(acc[mt][nt], al, bh + nt * 2);
                    mma_bf16(acc[mt][nt], ah, bl + nt * 2);
                }
            }
        }
        __syncthreads();
    }

    // ---- epilogue: store + BN-stat accumulation ----
#pragma unroll
    for (int mt = 0; mt < 4; ++mt) {
        int r0 = row0 + m0 + mt * 16 + (lane >> 2);
        int r1 = r0 + 8;
        int cb = n0 + (lane & 3) * 2;
        if (r0 < N) {
            float* o = g_out1 + (size_t)r0 * D + cb;
#pragma unroll
            for (int nt = 0; nt < 4; ++nt) {
                o[nt * 8 + 0] = acc[mt][nt][0];
                o[nt * 8 + 1] = acc[mt][nt][1];
            }
        }
        if (r1 < N) {
            float* o = g_out1 + (size_t)r1 * D + cb;
#pragma unroll
            for (int nt = 0; nt < 4; ++nt) {
                o[nt * 8 + 0] = acc[mt][nt][2];
                o[nt * 8 + 1] = acc[mt][nt][3];
            }
        }
    }
    // per-column stats: pad rows hold exact zeros -> safe unmasked
    {
        int cb = n0 + (lane & 3) * 2;
#pragma unroll
        for (int nt = 0; nt < 4; ++nt) {
            float cs0 = 0.f, cq0 = 0.f, cs1 = 0.f, cq1 = 0.f;
#pragma unroll
            for (int mt = 0; mt < 4; ++mt) {
                float a0 = acc[mt][nt][0], a2 = acc[mt][nt][2];
                float a1 = acc[mt][nt][1], a3 = acc[mt][nt][3];
                cs0 += a0 + a2; cq0 += a0 * a0 + a2 * a2;
                cs1 += a1 + a3; cq1 += a1 * a1 + a3 * a3;
            }
            atomicAdd(&s_sum[cb + nt * 8 + 0], cs0);
            atomicAdd(&s_sq [cb + nt * 8 + 0], cq0);
            atomicAdd(&s_sum[cb + nt * 8 + 1], cs1);
            atomicAdd(&s_sq [cb + nt * 8 + 1], cq1);
        }
    }
    __syncthreads();
    if (tid < D) {
        atomicAdd(&g_sum[tid], s_sum[tid]);
        atomicAdd(&g_sq [tid], s_sq[tid]);
    }
}

__global__ void finalize_kernel(const float* __restrict__ gamma,
                                const float* __restrict__ beta,
                                float invN)
{
    int c = threadIdx.x;
    if (c < D) {
        float mean = g_sum[c] * invN;
        float var  = g_sq[c] * invN - mean * mean;
        float rstd = rsqrtf(var + 1e-5f);
        float sc   = rstd * gamma[c];
        g_scale[c] = sc;
        g_shift[c] = beta[c] - mean * sc;
    }
}

// ============================================================
// fused MLP via mma.sync bf16x3: 128-row tile per CTA, 8 warps.
// ============================================================
__global__ __launch_bounds__(256) void mlp_mma_kernel(
    const float* __restrict__ x,
    float* __restrict__ out,
    int N)
{
    extern __shared__ __align__(16) __nv_bfloat16 sm[];
    __nv_bfloat16* Ahi = sm;
    __nv_bfloat16* Alo = Ahi + 128 * ASTRIDE;
    __nv_bfloat16* Thi = Alo + 128 * ASTRIDE;
    __nv_bfloat16* Tlo = Thi + 128 * ASTRIDE;
    __nv_bfloat16* Whi = Tlo + 128 * ASTRIDE;
    __nv_bfloat16* Wlo = Whi + 64 * ASTRIDE;
    __shared__ float s_sc[D], s_sh[D];

    const int tid  = threadIdx.x;
    const int wid  = tid >> 5;
    const int lane = tid & 31;
    const int row0 = blockIdx.x * 128;

    if (tid < D) { s_sc[tid] = g_scale[tid]; s_sh[tid] = g_shift[tid]; }
    __syncthreads();

    {
        const int r    = tid >> 1;
        const int half = tid & 1;
        const int row  = row0 + r;
        char* aH = (char*)(Ahi + r * ASTRIDE + half * 32);
        char* aL = (char*)(Alo + r * ASTRIDE + half * 32);
        if (row < N) {
            const float4* src = (const float4*)(g_out1 + (size_t)row * D + half * 32);
            const int cb = half * 32;
#pragma unroll
            for (int j = 0; j < 4; ++j) {
                float4 v0 = src[2 * j], v1 = src[2 * j + 1];
                int c = cb + j * 8;
                v0.x = v0.x * s_sc[c + 0] + s_sh[c + 0];
                v0.y = v0.y * s_sc[c + 1] + s_sh[c + 1];
                v0.z = v0.z * s_sc[c + 2] + s_sh[c + 2];
                v0.w = v0.w * s_sc[c + 3] + s_sh[c + 3];
                v1.x = v1.x * s_sc[c + 4] + s_sh[c + 4];
                v1.y = v1.y * s_sc[c + 5] + s_sh[c + 5];
                v1.z = v1.z * s_sc[c + 6] + s_sh[c + 6];
                v1.w = v1.w * s_sc[c + 7] + s_sh[c + 7];
                uint4 h, l;
                split2(v0.x, v0.y, h.x, l.x);
                split2(v0.z, v0.w, h.y, l.y);
                split2(v1.x, v1.y, h.z, l.z);
                split2(v1.z, v1.w, h.w, l.w);
                *(uint4*)(aH + j * 16) = h;
                *(uint4*)(aL + j * 16) = l;
            }
        } else {
            const uint4 z = make_uint4(0, 0, 0, 0);
#pragma unroll
            for (int j = 0; j < 4; ++j) {
                *(uint4*)(aH + j * 16) = z;
                *(uint4*)(aL + j * 16) = z;
            }
        }
    }

    const int m0 = (wid & 3) * 32;
    const int n0 = (wid >> 2) * 32;

    const uint32_t uAhi = smem_u32(Ahi), uAlo = smem_u32(Alo);
    const uint32_t uThi = smem_u32(Thi), uTlo = smem_u32(Tlo);
    const uint32_t uWhi = smem_u32(Whi), uWlo = smem_u32(Wlo);
    const uint32_t arow = (uint32_t)(m0 + (lane & 15));
    const uint32_t acol = (uint32_t)((lane >> 4) * 8);
    const uint32_t aA0 = (arow * ASTRIDE + acol) * 2;
    const uint32_t aA1 = ((arow + 16) * ASTRIDE + acol) * 2;
    const uint32_t brow = (uint32_t)(n0 + (lane & 7) + ((lane >> 4) << 3));
    const uint32_t bcol = (uint32_t)(((lane >> 3) & 1) * 8);
    const uint32_t aB0 = (brow * ASTRIDE + bcol) * 2;
    const uint32_t aB1 = ((brow + 16) * ASTRIDE + bcol) * 2;

    float acc2[2][4][4];
#pragma unroll
    for (int mt = 0; mt < 2; ++mt)
#pragma unroll
        for (int nt = 0; nt < 4; ++nt)
#pragma unroll
            for (int e = 0; e < 4; ++e) acc2[mt][nt][e] = 0.f;

    for (int cb4 = 0; cb4 < 4; ++cb4) {
        const int c0 = cb4 * 64;

        {
            const uint4* sh = (const uint4*)(g_W2bf_hi + (size_t)c0 * 64);
            const uint4* sl = (const uint4*)(g_W2bf_lo + (size_t)c0 * 64);
#pragma unroll
            for (int i = 0; i < 2; ++i) {
                int f = tid + i * 256;
                int r = f >> 3, c8 = f & 7;
                *(uint4*)((char*)(Whi + r * ASTRIDE) + c8 * 16) = sh[f];
                *(uint4*)((char*)(Wlo + r * ASTRIDE) + c8 * 16) = sl[f];
            }
        }
        __syncthreads();

        float acc1[2][4][4];
#pragma unroll
        for (int mt = 0; mt < 2; ++mt)
#pragma unroll
            for (int nt = 0; nt < 4; ++nt)
#pragma unroll
                for (int e = 0; e < 4; ++e) acc1[mt][nt][e] = 0.f;

#pragma unroll
        for (int kk = 0; kk < 4; ++kk) {
            const uint32_t ko = kk * 32;
            uint32_t ah[8], al[8], bh[8], bl[8];
            ldm_x4(ah,     uAhi + aA0 + ko);
            ldm_x4(ah + 4, uAhi + aA1 + ko);
            ldm_x4(al,     uAlo + aA0 + ko);
            ldm_x4(al + 4, uAlo + aA1 + ko);
            ldm_x4(bh,     uWhi + aB0 + ko);
            ldm_x4(bh + 4, uWhi + aB1 + ko);
            ldm_x4(bl,     uWlo + aB0 + ko);
            ldm_x4(bl + 4, uWlo + aB1 + ko);
#pragma unroll
            for (int mt = 0; mt < 2; ++mt) {
#pragma unroll
                for (int nt = 0; nt < 4; ++nt) {
                    mma_bf16(acc1[mt][nt], ah + mt * 4, bh + nt * 2);
                    mma_bf16(acc1[mt][nt], al + mt * 4, bh + nt * 2);
                    mma_bf16(acc1[mt][nt], ah + mt * 4, bl + nt * 2);
                }
            }
        }

#pragma unroll
        for (int mt = 0; mt < 2; ++mt) {
            int lr0 = m0 + mt * 16 + (lane >> 2);
            int lr1 = lr0 + 8;
            int cc  = n0 + (lane & 3) * 2;
#pragma unroll
            for (int nt = 0; nt < 4; ++nt) {
                float v0 = fmaxf(acc1[mt][nt][0], 0.f);
                float v1 = fmaxf(acc1[mt][nt][1], 0.f);
                float v2 = fmaxf(acc1[mt][nt][2], 0.f);
                float v3 = fmaxf(acc1[mt][nt][3], 0.f);
                uint32_t h, l;
                split2(v0, v1, h, l);
                *(uint32_t*)((char*)(Thi + lr0 * ASTRIDE + cc + nt * 8)) = h;
                *(uint32_t*)((char*)(Tlo + lr0 * ASTRIDE + cc + nt * 8)) = l;
                split2(v2, v3, h, l);
                *(uint32_t*)((char*)(Thi + lr1 * ASTRIDE + cc + nt * 8)) = h;
                *(uint32_t*)((char*)(Tlo + lr1 * ASTRIDE + cc + nt * 8)) = l;
            }
        }
        __syncthreads();

        {
#pragma unroll
            for (int i = 0; i < 2; ++i) {
                int f = tid + i * 256;
                int r = f >> 3, c8 = f & 7;
                *(uint4*)((char*)(Whi + r * ASTRIDE) + c8 * 16) =
                    *((const uint4*)(g_W3bf_hi + (size_t)r * 256 + c0) + c8);
                *(uint4*)((char*)(Wlo + r * ASTRIDE) + c8 * 16) =
                    *((const uint4*)(g_W3bf_lo + (size_t)r * 256 + c0) + c8);
            }
        }
        __syncthreads();

#pragma unroll
        for (int kk = 0; kk < 4; ++kk) {
            const uint32_t ko = kk * 32;
            uint32_t ah[8], al[8], bh[8], bl[8];
            ldm_x4(ah,     uThi + aA0 + ko);
            ldm_x4(ah + 4, uThi + aA1 + ko);
            ldm_x4(al,     uTlo + aA0 + ko);
            ldm_x4(al + 4, uTlo + aA1 + ko);
            ldm_x4(bh,     uWhi + aB0 + ko);
            ldm_x4(bh + 4, uWhi + aB1 + ko);
            ldm_x4(bl,     uWlo + aB0 + ko);
            ldm_x4(bl + 4, uWlo + aB1 + ko);
#pragma unroll
            for (int mt = 0; mt < 2; ++mt) {
#pragma unroll
                for (int nt = 0; nt < 4; ++nt) {
                    mma_bf16(acc2[mt][nt], ah + mt * 4, bh + nt * 2);
                    mma_bf16(acc2[mt][nt], al + mt * 4, bh + nt * 2);
                    mma_bf16(acc2[mt][nt], ah + mt * 4, bl + nt * 2);
                }
            }
        }
        __syncthreads();
    }

#pragma unroll
    for (int mt = 0; mt < 2; ++mt) {
        int r0 = row0 + m0 + mt * 16 + (lane >> 2);
        int r1 = r0 + 8;
        int cb = n0 + (lane & 3) * 2;
        if (r0 < N) {
            float* o = out + (size_t)r0 * D + cb;
            const float* xr = x + (size_t)r0 * D + cb;
#pragma unroll
            for (int nt = 0; nt < 4; ++nt) {
                float2 xv = *(const float2*)(xr + nt * 8);
                float2 ov = make_float2(acc2[mt][nt][0] + xv.x, acc2[mt][nt][1] + xv.y);
                *(float2*)(o + nt * 8) = ov;
            }
        }
        if (r1 < N) {
            float* o = out + (size_t)r1 * D + cb;
            const float* xr = x + (size_t)r1 * D + cb;
#pragma unroll
            for (int nt = 0; nt < 4; ++nt) {
                float2 xv = *(const float2*)(xr + nt * 8);
                float2 ov = make_float2(acc2[mt][nt][2] + xv.x, acc2[mt][nt][3] + xv.y);
                *(float2*)(o + nt * 8) = ov;
            }
        }
    }
}

// ============================================================
// launch
// ============================================================
extern "C" void kernel_launch(void* const* d_in, const int* in_sizes, int n_in,
                              void* d_out, int out_size)
{
    const float* x     = (const float*)d_in[0];
    const int*   nidx  = (const int*)  d_in[1];
    const int*   nmask = (const int*)  d_in[2];
    const float* W1    = (const float*)d_in[3];
    const float* gamma = (const float*)d_in[4];
    const float* beta  = (const float*)d_in[5];
    const float* W2    = (const float*)d_in[6];
    const float* W3    = (const float*)d_in[7];
    float* out = (float*)d_out;

    const int N = in_sizes[0] / D;
    const int K = in_sizes[1] / N;

    const int conv_smem = (256 * ASTRIDE * 2 + 64 * ASTRIDE * 2) * 2;
    cudaFuncSetAttribute(conv1_mma_kernel, cudaFuncAttributeMaxDynamicSharedMemorySize, conv_smem);
    const int mlp_smem = (128 * ASTRIDE * 4 + 64 * ASTRIDE * 2) * 2;
    cudaFuncSetAttribute(mlp_mma_kernel, cudaFuncAttributeMaxDynamicSharedMemorySize, mlp_smem);

    prep_w_kernel<<<K, 256>>>(W1, K);
    prep_w23_kernel<<<64, 256>>>(W2, W3);
    zero_stats_kernel<<<1, 64>>>();
    conv1_mma_kernel<<<(N + 255) / 256, 256, conv_smem>>>(x, nidx, nmask, N, K);
    finalize_kernel<<<1, 64>>>(gamma, beta, 1.0f / (float)N);
    mlp_mma_kernel<<<(N + 127) / 128, 256, mlp_smem>>>(x, out, N);
}

// round 6
// speedup vs baseline: 3.4848x; 1.3668x over previous
#include <cuda_runtime.h>
#include <cuda_fp16.h>
#include <cstdint>

#define D 64
#define MAXN 150208
#define KMAX 27

// ---- scratch (static device arrays: allocation-free) ----
__device__ float g_out1[(size_t)MAXN * D];   // conv1 output
__device__ float g_sum[D];
__device__ float g_sq[D];
__device__ float g_scale[D];
__device__ float g_shift[D];
__device__ __half g_xh[(size_t)MAXN * D];    // x rounded to fp16
// W1 transposed to [k][n_out][c_in], split into fp16 hi/lo
__device__ __half g_W1h_hi[(size_t)KMAX * 4096];
__device__ __half g_W1h_lo[(size_t)KMAX * 4096];
// W2^T [256][64], W3^T [64][256] split into fp16 hi/lo
__device__ __half g_W2h_hi[256 * 64];
__device__ __half g_W2h_lo[256 * 64];
__device__ __half g_W3h_hi[64 * 256];
__device__ __half g_W3h_lo[64 * 256];

// ============================================================
// helpers
// ============================================================
__device__ __forceinline__ uint32_t smem_u32(const void* p) {
    uint32_t a;
    asm("{ .reg .u64 t; cvta.to.shared.u64 t, %1; cvt.u32.u64 %0, t; }" : "=r"(a) : "l"(p));
    return a;
}

__device__ __forceinline__ void ldm_x4(uint32_t* r, uint32_t addr) {
    asm volatile("ldmatrix.sync.aligned.m8n8.x4.shared.b16 {%0,%1,%2,%3}, [%4];"
                 : "=r"(r[0]), "=r"(r[1]), "=r"(r[2]), "=r"(r[3]) : "r"(addr));
}

__device__ __forceinline__ void mma_f16(float* d, const uint32_t* a, const uint32_t* b) {
    asm volatile(
        "mma.sync.aligned.m16n8k16.row.col.f32.f16.f16.f32 "
        "{%0,%1,%2,%3},{%4,%5,%6,%7},{%8,%9},{%0,%1,%2,%3};"
        : "+f"(d[0]), "+f"(d[1]), "+f"(d[2]), "+f"(d[3])
        : "r"(a[0]), "r"(a[1]), "r"(a[2]), "r"(a[3]), "r"(b[0]), "r"(b[1]));
}

// ============================================================
// small kernels
// ============================================================
__global__ void zero_stats_kernel() {
    int t = threadIdx.x;
    if (t < D) { g_sum[t] = 0.f; g_sq[t] = 0.f; }
}

// x fp32 -> fp16 (8 elems per thread)
__global__ void prep_x_kernel(const float* __restrict__ x, int total8) {
    int e = blockIdx.x * blockDim.x + threadIdx.x;
    if (e >= total8) return;
    const float4* s = (const float4*)x + 2 * e;
    float4 a = s[0], b = s[1];
    uint4 o;
    __half2 h;
    h = __floats2half2_rn(a.x, a.y); o.x = *(uint32_t*)&h;
    h = __floats2half2_rn(a.z, a.w); o.y = *(uint32_t*)&h;
    h = __floats2half2_rn(b.x, b.y); o.z = *(uint32_t*)&h;
    h = __floats2half2_rn(b.z, b.w); o.w = *(uint32_t*)&h;
    ((uint4*)g_xh)[e] = o;
}

// W1[k][c][n] -> Wt[k][n][c] fp16 hi/lo
__global__ void prep_w_kernel(const float* __restrict__ W1, int K) {
    int k = blockIdx.x;
    if (k >= K) return;
    const float* Wk = W1 + (size_t)k * 4096;
    __half* dh = g_W1h_hi + (size_t)k * 4096;
    __half* dl = g_W1h_lo + (size_t)k * 4096;
    for (int e = threadIdx.x; e < 4096; e += blockDim.x) {
        int n = e >> 6, c = e & 63;
        float v = Wk[c * 64 + n];
        __half hi = __float2half_rn(v);
        float lo = v - __half2float(hi);
        dh[n * 64 + c] = hi;
        dl[n * 64 + c] = __float2half_rn(lo);
    }
}

// W2 [64][256] -> W2t [n][c]; W3 [256][64] -> W3t [n][c]; fp16 hi/lo
__global__ void prep_w23_kernel(const float* __restrict__ W2,
                                const float* __restrict__ W3) {
    int e = blockIdx.x * blockDim.x + threadIdx.x;
    if (e < 256 * 64) {
        int n = e >> 6, c = e & 63;
        float v = W2[(size_t)c * 256 + n];
        __half hi = __float2half_rn(v);
        float lo = v - __half2float(hi);
        g_W2h_hi[n * 64 + c] = hi;
        g_W2h_lo[n * 64 + c] = __float2half_rn(lo);
    }
    if (e < 64 * 256) {
        int n = e >> 8, c = e & 255;
        float v = W3[(size_t)c * 64 + n];
        __half hi = __float2half_rn(v);
        float lo = v - __half2float(hi);
        g_W3h_hi[n * 256 + c] = hi;
        g_W3h_lo[n * 256 + c] = __float2half_rn(lo);
    }
}

// ============================================================
// conv1 via mma.sync fp16 (A single, W hi/lo, 2 terms):
// 256x64 tile per CTA, 8 warps, warp tile 64x32.
// Also accumulates per-channel BN stats (pad rows are exact zeros).
// ============================================================
#define ASTRIDE 72
__global__ __launch_bounds__(256, 2) void conv1_mma_kernel(
    const int*   __restrict__ nbr_idx,
    const int*   __restrict__ nbr_mask,
    int N, int K)
{
    extern __shared__ __align__(16) __half sm[];
    __half* Ah  = sm;                      // 256*72
    __half* Whi = Ah  + 256 * ASTRIDE;     // 64*72
    __half* Wlo = Whi + 64 * ASTRIDE;      // 64*72
    __shared__ float s_sum[D], s_sq[D];

    const int tid  = threadIdx.x;
    const int wid  = tid >> 5;
    const int lane = tid & 31;
    const int row0 = blockIdx.x * 256;

    if (tid < D) { s_sum[tid] = 0.f; s_sq[tid] = 0.f; }

    // gather: 1 thread per row (64 fp16 = 128B)
    const int grow = row0 + tid;
    uint4* aDst = (uint4*)(Ah + tid * ASTRIDE);

    // warp tiling: 4 m-groups x 2 n-groups
    const int m0 = (wid & 3) * 64;
    const int n0 = (wid >> 2) * 32;

    const uint32_t uAh = smem_u32(Ah);
    const uint32_t uWhi = smem_u32(Whi), uWlo = smem_u32(Wlo);
    const uint32_t acol = (uint32_t)((lane >> 4) * 8);
    uint32_t aA[4];
#pragma unroll
    for (int mt = 0; mt < 4; ++mt)
        aA[mt] = (uint32_t)(((m0 + mt * 16 + (lane & 15)) * ASTRIDE + acol) * 2);
    const uint32_t brow = (uint32_t)(n0 + (lane & 7) + ((lane >> 4) << 3));
    const uint32_t bcol = (uint32_t)(((lane >> 3) & 1) * 8);
    const uint32_t aB0 = (brow * ASTRIDE + bcol) * 2;
    const uint32_t aB1 = ((brow + 16) * ASTRIDE + bcol) * 2;

    float acc[4][4][4];
#pragma unroll
    for (int mt = 0; mt < 4; ++mt)
#pragma unroll
        for (int nt = 0; nt < 4; ++nt)
#pragma unroll
            for (int e = 0; e < 4; ++e) acc[mt][nt][e] = 0.f;

    for (int k = 0; k < K; ++k) {
        // ---- W tiles (64x64 fp16 hi/lo, 8KB each) ----
        {
            const uint4* sh = (const uint4*)(g_W1h_hi + (size_t)k * 4096);
            const uint4* sl = (const uint4*)(g_W1h_lo + (size_t)k * 4096);
#pragma unroll
            for (int i = 0; i < 2; ++i) {
                int f = tid + i * 256;   // 0..511
                int r = f >> 3, c8 = f & 7;
                *(uint4*)((char*)(Whi + r * ASTRIDE) + c8 * 16) = sh[f];
                *(uint4*)((char*)(Wlo + r * ASTRIDE) + c8 * 16) = sl[f];
            }
        }

        // ---- masked gather (fp16 row copy, no split) ----
        int m = 0;
        const uint4* src = nullptr;
        if (grow < N) {
            m = nbr_mask[(size_t)k * N + grow];
            if (m) src = (const uint4*)(g_xh + (size_t)nbr_idx[(size_t)k * N + grow] * D);
        }
        if (m) {
#pragma unroll
            for (int j = 0; j < 8; ++j) aDst[j] = src[j];
        } else {
            const uint4 z = make_uint4(0, 0, 0, 0);
#pragma unroll
            for (int j = 0; j < 8; ++j) aDst[j] = z;
        }
        __syncthreads();

        // ---- mma: acc += A*Whi + A*Wlo ----
#pragma unroll
        for (int kk = 0; kk < 4; ++kk) {
            const uint32_t ko = kk * 32;
            uint32_t bh[8], bl[8];
            ldm_x4(bh,     uWhi + aB0 + ko);
            ldm_x4(bh + 4, uWhi + aB1 + ko);
            ldm_x4(bl,     uWlo + aB0 + ko);
            ldm_x4(bl + 4, uWlo + aB1 + ko);
#pragma unroll
            for (int mt = 0; mt < 4; ++mt) {
                uint32_t ah[4];
                ldm_x4(ah, uAh + aA[mt] + ko);
#pragma unroll
                for (int nt = 0; nt < 4; ++nt) {
                    mma_f16(acc[mt][nt], ah, bh + nt * 2);
                    mma_f16(acc[mt][nt], ah, bl + nt * 2);
                }
            }
        }
        __syncthreads();
    }

    // ---- epilogue: store + BN-stat accumulation ----
#pragma unroll
    for (int mt = 0; mt < 4; ++mt) {
        int r0 = row0 + m0 + mt * 16 + (lane >> 2);
        int r1 = r0 + 8;
        int cb = n0 + (lane & 3) * 2;
        if (r0 < N) {
            float* o = g_out1 + (size_t)r0 * D + cb;
#pragma unroll
            for (int nt = 0; nt < 4; ++nt) {
                o[nt * 8 + 0] = acc[mt][nt][0];
                o[nt * 8 + 1] = acc[mt][nt][1];
            }
        }
        if (r1 < N) {
            float* o = g_out1 + (size_t)r1 * D + cb;
#pragma unroll
            for (int nt = 0; nt < 4; ++nt) {
                o[nt * 8 + 0] = acc[mt][nt][2];
                o[nt * 8 + 1] = acc[mt][nt][3];
            }
        }
    }
    // per-column stats: pad rows hold exact zeros -> safe unmasked
    {
        int cb = n0 + (lane & 3) * 2;
#pragma unroll
        for (int nt = 0; nt < 4; ++nt) {
            float cs0 = 0.f, cq0 = 0.f, cs1 = 0.f, cq1 = 0.f;
#pragma unroll
            for (int mt = 0; mt < 4; ++mt) {
                float a0 = acc[mt][nt][0], a2 = acc[mt][nt][2];
                float a1 = acc[mt][nt][1], a3 = acc[mt][nt][3];
                cs0 += a0 + a2; cq0 += a0 * a0 + a2 * a2;
                cs1 += a1 + a3; cq1 += a1 * a1 + a3 * a3;
            }
            atomicAdd(&s_sum[cb + nt * 8 + 0], cs0);
            atomicAdd(&s_sq [cb + nt * 8 + 0], cq0);
            atomicAdd(&s_sum[cb + nt * 8 + 1], cs1);
            atomicAdd(&s_sq [cb + nt * 8 + 1], cq1);
        }
    }
    __syncthreads();
    if (tid < D) {
        atomicAdd(&g_sum[tid], s_sum[tid]);
        atomicAdd(&g_sq [tid], s_sq[tid]);
    }
}

__global__ void finalize_kernel(const float* __restrict__ gamma,
                                const float* __restrict__ beta,
                                float invN)
{
    int c = threadIdx.x;
    if (c < D) {
        float mean = g_sum[c] * invN;
        float var  = g_sq[c] * invN - mean * mean;
        float rstd = rsqrtf(var + 1e-5f);
        float sc   = rstd * gamma[c];
        g_scale[c] = sc;
        g_shift[c] = beta[c] - mean * sc;
    }
}

// ============================================================
// fused MLP via mma.sync fp16 (A/T single, W hi/lo):
// 128-row tile per CTA, 8 warps, warp tile 32x32.
// ============================================================
__global__ __launch_bounds__(256) void mlp_mma_kernel(
    const float* __restrict__ x,
    float* __restrict__ out,
    int N)
{
    extern __shared__ __align__(16) __half sm[];
    __half* Ah  = sm;                      // 128*72
    __half* Th  = Ah  + 128 * ASTRIDE;     // 128*72
    __half* Whi = Th  + 128 * ASTRIDE;     // 64*72
    __half* Wlo = Whi + 64 * ASTRIDE;      // 64*72
    __shared__ float s_sc[D], s_sh[D];

    const int tid  = threadIdx.x;
    const int wid  = tid >> 5;
    const int lane = tid & 31;
    const int row0 = blockIdx.x * 128;

    if (tid < D) { s_sc[tid] = g_scale[tid]; s_sh[tid] = g_shift[tid]; }
    __syncthreads();

    // ---- build A = fp16(BN(out1 tile)) ----
    {
        const int r    = tid >> 1;
        const int half = tid & 1;
        const int row  = row0 + r;
        uint2* aDst = (uint2*)((char*)(Ah + r * ASTRIDE) + half * 64);
        if (row < N) {
            const float4* src = (const float4*)(g_out1 + (size_t)row * D + half * 32);
            const int cb = half * 32;
#pragma unroll
            for (int j = 0; j < 4; ++j) {
                float4 v0 = src[2 * j], v1 = src[2 * j + 1];
                int c = cb + j * 8;
                v0.x = v0.x * s_sc[c + 0] + s_sh[c + 0];
                v0.y = v0.y * s_sc[c + 1] + s_sh[c + 1];
                v0.z = v0.z * s_sc[c + 2] + s_sh[c + 2];
                v0.w = v0.w * s_sc[c + 3] + s_sh[c + 3];
                v1.x = v1.x * s_sc[c + 4] + s_sh[c + 4];
                v1.y = v1.y * s_sc[c + 5] + s_sh[c + 5];
                v1.z = v1.z * s_sc[c + 6] + s_sh[c + 6];
                v1.w = v1.w * s_sc[c + 7] + s_sh[c + 7];
                uint2 o;
                __half2 h;
                h = __floats2half2_rn(v0.x, v0.y); o.x = *(uint32_t*)&h;
                h = __floats2half2_rn(v0.z, v0.w); o.x = o.x; // keep order
                uint32_t t0 = o.x;
                h = __floats2half2_rn(v0.z, v0.w); uint32_t t1 = *(uint32_t*)&h;
                o.x = t0; o.y = t1;
                aDst[2 * j] = o;
                h = __floats2half2_rn(v1.x, v1.y); o.x = *(uint32_t*)&h;
                h = __floats2half2_rn(v1.z, v1.w); o.y = *(uint32_t*)&h;
                aDst[2 * j + 1] = o;
            }
        } else {
            const uint2 z = make_uint2(0, 0);
#pragma unroll
            for (int j = 0; j < 8; ++j) aDst[j] = z;
        }
    }

    const int m0 = (wid & 3) * 32;
    const int n0 = (wid >> 2) * 32;

    const uint32_t uAh = smem_u32(Ah);
    const uint32_t uTh = smem_u32(Th);
    const uint32_t uWhi = smem_u32(Whi), uWlo = smem_u32(Wlo);
    const uint32_t arow = (uint32_t)(m0 + (lane & 15));
    const uint32_t acol = (uint32_t)((lane >> 4) * 8);
    const uint32_t aA0 = (arow * ASTRIDE + acol) * 2;
    const uint32_t aA1 = ((arow + 16) * ASTRIDE + acol) * 2;
    const uint32_t brow = (uint32_t)(n0 + (lane & 7) + ((lane >> 4) << 3));
    const uint32_t bcol = (uint32_t)(((lane >> 3) & 1) * 8);
    const uint32_t aB0 = (brow * ASTRIDE + bcol) * 2;
    const uint32_t aB1 = ((brow + 16) * ASTRIDE + bcol) * 2;

    float acc2[2][4][4];
#pragma unroll
    for (int mt = 0; mt < 2; ++mt)
#pragma unroll
        for (int nt = 0; nt < 4; ++nt)
#pragma unroll
            for (int e = 0; e < 4; ++e) acc2[mt][nt][e] = 0.f;

    for (int cb4 = 0; cb4 < 4; ++cb4) {
        const int c0 = cb4 * 64;

        // ---- W2 chunk hi/lo ----
        {
            const uint4* sh = (const uint4*)(g_W2h_hi + (size_t)c0 * 64);
            const uint4* sl = (const uint4*)(g_W2h_lo + (size_t)c0 * 64);
#pragma unroll
            for (int i = 0; i < 2; ++i) {
                int f = tid + i * 256;
                int r = f >> 3, c8 = f & 7;
                *(uint4*)((char*)(Whi + r * ASTRIDE) + c8 * 16) = sh[f];
                *(uint4*)((char*)(Wlo + r * ASTRIDE) + c8 * 16) = sl[f];
            }
        }
        __syncthreads();

        // ---- GEMM1 chunk: acc1 = A @ W2c (2-term) ----
        float acc1[2][4][4];
#pragma unroll
        for (int mt = 0; mt < 2; ++mt)
#pragma unroll
            for (int nt = 0; nt < 4; ++nt)
#pragma unroll
                for (int e = 0; e < 4; ++e) acc1[mt][nt][e] = 0.f;

#pragma unroll
        for (int kk = 0; kk < 4; ++kk) {
            const uint32_t ko = kk * 32;
            uint32_t ah[8], bh[8], bl[8];
            ldm_x4(ah,     uAh + aA0 + ko);
            ldm_x4(ah + 4, uAh + aA1 + ko);
            ldm_x4(bh,     uWhi + aB0 + ko);
            ldm_x4(bh + 4, uWhi + aB1 + ko);
            ldm_x4(bl,     uWlo + aB0 + ko);
            ldm_x4(bl + 4, uWlo + aB1 + ko);
#pragma unroll
            for (int mt = 0; mt < 2; ++mt) {
#pragma unroll
                for (int nt = 0; nt < 4; ++nt) {
                    mma_f16(acc1[mt][nt], ah + mt * 4, bh + nt * 2);
                    mma_f16(acc1[mt][nt], ah + mt * 4, bl + nt * 2);
                }
            }
        }

        // ---- relu + fp16 -> T ----
#pragma unroll
        for (int mt = 0; mt < 2; ++mt) {
            int lr0 = m0 + mt * 16 + (lane >> 2);
            int lr1 = lr0 + 8;
            int cc  = n0 + (lane & 3) * 2;
#pragma unroll
            for (int nt = 0; nt < 4; ++nt) {
                __half2 h;
                h = __floats2half2_rn(fmaxf(acc1[mt][nt][0], 0.f),
                                      fmaxf(acc1[mt][nt][1], 0.f));
                *(uint32_t*)((char*)Th + (lr0 * ASTRIDE + cc + nt * 8) * 2) = *(uint32_t*)&h;
                h = __floats2half2_rn(fmaxf(acc1[mt][nt][2], 0.f),
                                      fmaxf(acc1[mt][nt][3], 0.f));
                *(uint32_t*)((char*)Th + (lr1 * ASTRIDE + cc + nt * 8) * 2) = *(uint32_t*)&h;
            }
        }
        __syncthreads();   // T visible; all warps done with W2 chunk

        // ---- W3 chunk hi/lo ----
        {
#pragma unroll
            for (int i = 0; i < 2; ++i) {
                int f = tid + i * 256;
                int r = f >> 3, c8 = f & 7;
                *(uint4*)((char*)(Whi + r * ASTRIDE) + c8 * 16) =
                    *((const uint4*)(g_W3h_hi + (size_t)r * 256 + c0) + c8);
                *(uint4*)((char*)(Wlo + r * ASTRIDE) + c8 * 16) =
                    *((const uint4*)(g_W3h_lo + (size_t)r * 256 + c0) + c8);
            }
        }
        __syncthreads();

        // ---- GEMM2 chunk: acc2 += T @ W3c (2-term) ----
#pragma unroll
        for (int kk = 0; kk < 4; ++kk) {
            const uint32_t ko = kk * 32;
            uint32_t ah[8], bh[8], bl[8];
            ldm_x4(ah,     uTh + aA0 + ko);
            ldm_x4(ah + 4, uTh + aA1 + ko);
            ldm_x4(bh,     uWhi + aB0 + ko);
            ldm_x4(bh + 4, uWhi + aB1 + ko);
            ldm_x4(bl,     uWlo + aB0 + ko);
            ldm_x4(bl + 4, uWlo + aB1 + ko);
#pragma unroll
            for (int mt = 0; mt < 2; ++mt) {
#pragma unroll
                for (int nt = 0; nt < 4; ++nt) {
                    mma_f16(acc2[mt][nt], ah + mt * 4, bh + nt * 2);
                    mma_f16(acc2[mt][nt], ah + mt * 4, bl + nt * 2);
                }
            }
        }
        __syncthreads();
    }

    // ---- epilogue: residual + store ----
#pragma unroll
    for (int mt = 0; mt < 2; ++mt) {
        int r0 = row0 + m0 + mt * 16 + (lane >> 2);
        int r1 = r0 + 8;
        int cb = n0 + (lane & 3) * 2;
        if (r0 < N) {
            float* o = out + (size_t)r0 * D + cb;
            const float* xr = x + (size_t)r0 * D + cb;
#pragma unroll
            for (int nt = 0; nt < 4; ++nt) {
                float2 xv = *(const float2*)(xr + nt * 8);
                float2 ov = make_float2(acc2[mt][nt][0] + xv.x, acc2[mt][nt][1] + xv.y);
                *(float2*)(o + nt * 8) = ov;
            }
        }
        if (r1 < N) {
            float* o = out + (size_t)r1 * D + cb;
            const float* xr = x + (size_t)r1 * D + cb;
#pragma unroll
            for (int nt = 0; nt < 4; ++nt) {
                float2 xv = *(const float2*)(xr + nt * 8);
                float2 ov = make_float2(acc2[mt][nt][2] + xv.x, acc2[mt][nt][3] + xv.y);
                *(float2*)(o + nt * 8) = ov;
            }
        }
    }
}

// ============================================================
// launch
// ============================================================
extern "C" void kernel_launch(void* const* d_in, const int* in_sizes, int n_in,
                              void* d_out, int out_size)
{
    const float* x     = (const float*)d_in[0];
    const int*   nidx  = (const int*)  d_in[1];
    const int*   nmask = (const int*)  d_in[2];
    const float* W1    = (const float*)d_in[3];
    const float* gamma = (const float*)d_in[4];
    const float* beta  = (const float*)d_in[5];
    const float* W2    = (const float*)d_in[6];
    const float* W3    = (const float*)d_in[7];
    float* out = (float*)d_out;

    const int N = in_sizes[0] / D;
    const int K = in_sizes[1] / N;

    const int conv_smem = (256 * ASTRIDE + 64 * ASTRIDE * 2) * 2;   // A + Whi + Wlo, fp16
    cudaFuncSetAttribute(conv1_mma_kernel, cudaFuncAttributeMaxDynamicSharedMemorySize, conv_smem);
    const int mlp_smem = (128 * ASTRIDE * 2 + 64 * ASTRIDE * 2) * 2; // A + T + Whi + Wlo
    cudaFuncSetAttribute(mlp_mma_kernel, cudaFuncAttributeMaxDynamicSharedMemorySize, mlp_smem);

    const int total8 = N * D / 8;
    prep_x_kernel<<<(total8 + 255) / 256, 256>>>(x, total8);
    prep_w_kernel<<<K, 256>>>(W1, K);
    prep_w23_kernel<<<64, 256>>>(W2, W3);
    zero_stats_kernel<<<1, 64>>>();
    conv1_mma_kernel<<<(N + 255) / 256, 256, conv_smem>>>(nidx, nmask, N, K);
    finalize_kernel<<<1, 64>>>(gamma, beta, 1.0f / (float)N);
    mlp_mma_kernel<<<(N + 127) / 128, 256, mlp_smem>>>(x, out, N);
}

// round 7
// speedup vs baseline: 3.9408x; 1.1309x over previous
#include <cuda_runtime.h>
#include <cuda_fp16.h>
#include <cstdint>

#define D 64
#define MAXN 150208
#define KMAX 27

// ---- scratch (static device arrays: allocation-free) ----
__device__ __half g_out1h[(size_t)MAXN * D];  // conv1 output (fp16)
__device__ float g_sum[D];
__device__ float g_sq[D];
__device__ float g_bias[256];                 // sh @ W2
__device__ __half g_xh[(size_t)MAXN * D];     // x rounded to fp16
__device__ __half g_W1h[(size_t)KMAX * 4096]; // W1^T [k][n][c] fp16
__device__ __half g_W2h[256 * 64];            // (sc*W2)^T [n][c] fp16 (post-BN fold)
__device__ __half g_W3h[64 * 256];            // W3^T [n][c] fp16

// ============================================================
// helpers
// ============================================================
__device__ __forceinline__ uint32_t smem_u32(const void* p) {
    uint32_t a;
    asm("{ .reg .u64 t; cvta.to.shared.u64 t, %1; cvt.u32.u64 %0, t; }" : "=r"(a) : "l"(p));
    return a;
}

__device__ __forceinline__ void ldm_x4(uint32_t* r, uint32_t addr) {
    asm volatile("ldmatrix.sync.aligned.m8n8.x4.shared.b16 {%0,%1,%2,%3}, [%4];"
                 : "=r"(r[0]), "=r"(r[1]), "=r"(r[2]), "=r"(r[3]) : "r"(addr));
}

__device__ __forceinline__ void mma_f16(float* d, const uint32_t* a, const uint32_t* b) {
    asm volatile(
        "mma.sync.aligned.m16n8k16.row.col.f32.f16.f16.f32 "
        "{%0,%1,%2,%3},{%4,%5,%6,%7},{%8,%9},{%0,%1,%2,%3};"
        : "+f"(d[0]), "+f"(d[1]), "+f"(d[2]), "+f"(d[3])
        : "r"(a[0]), "r"(a[1]), "r"(a[2]), "r"(a[3]), "r"(b[0]), "r"(b[1]));
}

// ============================================================
// prep kernels
// ============================================================
// x fp32 -> fp16 (8 elems per thread); block 0 also zeroes stats
__global__ void prep_x_kernel(const float* __restrict__ x, int total8) {
    if (blockIdx.x == 0 && threadIdx.x < D) {
        g_sum[threadIdx.x] = 0.f;
        g_sq[threadIdx.x] = 0.f;
    }
    int e = blockIdx.x * blockDim.x + threadIdx.x;
    if (e >= total8) return;
    const float4* s = (const float4*)x + 2 * e;
    float4 a = s[0], b = s[1];
    uint4 o;
    __half2 h;
    h = __floats2half2_rn(a.x, a.y); o.x = *(uint32_t*)&h;
    h = __floats2half2_rn(a.z, a.w); o.y = *(uint32_t*)&h;
    h = __floats2half2_rn(b.x, b.y); o.z = *(uint32_t*)&h;
    h = __floats2half2_rn(b.z, b.w); o.w = *(uint32_t*)&h;
    ((uint4*)g_xh)[e] = o;
}

// W1[k][c][n] -> W1t[k][n][c] fp16;  W3[c][n] -> W3t[n][c] fp16
__global__ void prep_w_kernel(const float* __restrict__ W1,
                              const float* __restrict__ W3, int K) {
    int k = blockIdx.x;
    if (k < K) {
        const float* Wk = W1 + (size_t)k * 4096;
        __half* dh = g_W1h + (size_t)k * 4096;
        for (int e = threadIdx.x; e < 4096; e += blockDim.x) {
            int n = e >> 6, c = e & 63;
            dh[n * 64 + c] = __float2half_rn(Wk[c * 64 + n]);
        }
    }
    if (blockIdx.x == 0) {
        for (int e = threadIdx.x; e < 64 * 256; e += blockDim.x) {
            int n = e >> 8, c = e & 255;
            g_W3h[n * 256 + c] = __float2half_rn(W3[(size_t)c * 64 + n]);
        }
    }
}

// ============================================================
// conv1 via mma.sync fp16: 256x64 tile per CTA, 8 warps,
// warp tile 64x32. Accumulates per-channel BN stats.
// ============================================================
#define ASTRIDE 72
__global__ __launch_bounds__(256, 2) void conv1_mma_kernel(
    const int*   __restrict__ nbr_idx,
    const int*   __restrict__ nbr_mask,
    int N, int K)
{
    extern __shared__ __align__(16) __half sm[];
    __half* Ah = sm;                      // 256*72
    __half* Wh = Ah + 256 * ASTRIDE;      // 64*72
    __shared__ float s_sum[D], s_sq[D];

    const int tid  = threadIdx.x;
    const int wid  = tid >> 5;
    const int lane = tid & 31;
    const int row0 = blockIdx.x * 256;

    if (tid < D) { s_sum[tid] = 0.f; s_sq[tid] = 0.f; }

    // gather: 1 thread per row (64 fp16 = 128B)
    const int grow = row0 + tid;
    uint4* aDst = (uint4*)(Ah + tid * ASTRIDE);

    const int m0 = (wid & 3) * 64;
    const int n0 = (wid >> 2) * 32;

    const uint32_t uAh = smem_u32(Ah);
    const uint32_t uWh = smem_u32(Wh);
    const uint32_t acol = (uint32_t)((lane >> 4) * 8);
    uint32_t aA[4];
#pragma unroll
    for (int mt = 0; mt < 4; ++mt)
        aA[mt] = (uint32_t)(((m0 + mt * 16 + (lane & 15)) * ASTRIDE + acol) * 2);
    const uint32_t brow = (uint32_t)(n0 + (lane & 7) + ((lane >> 4) << 3));
    const uint32_t bcol = (uint32_t)(((lane >> 3) & 1) * 8);
    const uint32_t aB0 = (brow * ASTRIDE + bcol) * 2;
    const uint32_t aB1 = ((brow + 16) * ASTRIDE + bcol) * 2;

    float acc[4][4][4];
#pragma unroll
    for (int mt = 0; mt < 4; ++mt)
#pragma unroll
        for (int nt = 0; nt < 4; ++nt)
#pragma unroll
            for (int e = 0; e < 4; ++e) acc[mt][nt][e] = 0.f;

    for (int k = 0; k < K; ++k) {
        // ---- W tile (64x64 fp16, 8KB) ----
        {
            const uint4* sh = (const uint4*)(g_W1h + (size_t)k * 4096);
            {
                int f = tid;              // 0..255
                int r = f >> 2, c8 = f & 3;
                // 512 uint4 total: 2 per thread
                *(uint4*)((char*)(Wh + (tid >> 3) * ASTRIDE) + (tid & 7) * 16) = sh[tid];
                int f2 = tid + 256;
                *(uint4*)((char*)(Wh + (f2 >> 3) * ASTRIDE) + (f2 & 7) * 16) = sh[f2];
                (void)r; (void)c8;
            }
        }

        // ---- masked gather (fp16 row copy) ----
        int m = 0;
        const uint4* src = nullptr;
        if (grow < N) {
            m = nbr_mask[(size_t)k * N + grow];
            if (m) src = (const uint4*)(g_xh + (size_t)nbr_idx[(size_t)k * N + grow] * D);
        }
        if (m) {
#pragma unroll
            for (int j = 0; j < 8; ++j) aDst[j] = src[j];
        } else {
            const uint4 z = make_uint4(0, 0, 0, 0);
#pragma unroll
            for (int j = 0; j < 8; ++j) aDst[j] = z;
        }
        __syncthreads();

        // ---- mma: acc += A*W ----
#pragma unroll
        for (int kk = 0; kk < 4; ++kk) {
            const uint32_t ko = kk * 32;
            uint32_t bh[8];
            ldm_x4(bh,     uWh + aB0 + ko);
            ldm_x4(bh + 4, uWh + aB1 + ko);
#pragma unroll
            for (int mt = 0; mt < 4; ++mt) {
                uint32_t ah[4];
                ldm_x4(ah, uAh + aA[mt] + ko);
#pragma unroll
                for (int nt = 0; nt < 4; ++nt)
                    mma_f16(acc[mt][nt], ah, bh + nt * 2);
            }
        }
        __syncthreads();
    }

    // ---- epilogue: fp16 store + BN-stat accumulation ----
#pragma unroll
    for (int mt = 0; mt < 4; ++mt) {
        int r0 = row0 + m0 + mt * 16 + (lane >> 2);
        int r1 = r0 + 8;
        int cb = n0 + (lane & 3) * 2;
        if (r0 < N) {
            __half* o = g_out1h + (size_t)r0 * D + cb;
#pragma unroll
            for (int nt = 0; nt < 4; ++nt)
                *(__half2*)(o + nt * 8) = __floats2half2_rn(acc[mt][nt][0], acc[mt][nt][1]);
        }
        if (r1 < N) {
            __half* o = g_out1h + (size_t)r1 * D + cb;
#pragma unroll
            for (int nt = 0; nt < 4; ++nt)
                *(__half2*)(o + nt * 8) = __floats2half2_rn(acc[mt][nt][2], acc[mt][nt][3]);
        }
    }
    // per-column stats (pad rows are exact zeros -> safe unmasked)
    {
        int cb = n0 + (lane & 3) * 2;
#pragma unroll
        for (int nt = 0; nt < 4; ++nt) {
            float cs0 = 0.f, cq0 = 0.f, cs1 = 0.f, cq1 = 0.f;
#pragma unroll
            for (int mt = 0; mt < 4; ++mt) {
                float a0 = acc[mt][nt][0], a2 = acc[mt][nt][2];
                float a1 = acc[mt][nt][1], a3 = acc[mt][nt][3];
                cs0 += a0 + a2; cq0 += a0 * a0 + a2 * a2;
                cs1 += a1 + a3; cq1 += a1 * a1 + a3 * a3;
            }
            atomicAdd(&s_sum[cb + nt * 8 + 0], cs0);
            atomicAdd(&s_sq [cb + nt * 8 + 0], cq0);
            atomicAdd(&s_sum[cb + nt * 8 + 1], cs1);
            atomicAdd(&s_sq [cb + nt * 8 + 1], cq1);
        }
    }
    __syncthreads();
    if (tid < D) {
        atomicAdd(&g_sum[tid], s_sum[tid]);
        atomicAdd(&g_sq [tid], s_sq[tid]);
    }
}

// ============================================================
// finalize: BN scale/shift -> fold into W2 (fp16) + bias vector
// ============================================================
__global__ __launch_bounds__(256) void finalize_kernel(
    const float* __restrict__ gamma,
    const float* __restrict__ beta,
    const float* __restrict__ W2,
    float invN)
{
    __shared__ float s_sc[D], s_sh[D];
    int t = threadIdx.x;
    if (t < D) {
        float mean = g_sum[t] * invN;
        float var  = g_sq[t] * invN - mean * mean;
        float rstd = rsqrtf(var + 1e-5f);
        float sc   = rstd * gamma[t];
        s_sc[t] = sc;
        s_sh[t] = beta[t] - mean * sc;
    }
    __syncthreads();
    // t = output column n of W2 (0..255)
    float b = 0.f;
    __half* dst = g_W2h + t * 64;
    for (int c = 0; c < 64; ++c) {
        float w = W2[(size_t)c * 256 + t];
        dst[c] = __float2half_rn(s_sc[c] * w);
        b += s_sh[c] * w;
    }
    g_bias[t] = b;
}

// ============================================================
// fused MLP via mma.sync fp16: 128-row tile per CTA, 8 warps.
// out = relu(out1h @ W2' + bias) @ W3 + x
// ============================================================
__global__ __launch_bounds__(256) void mlp_mma_kernel(
    const float* __restrict__ x,
    float* __restrict__ out,
    int N)
{
    extern __shared__ __align__(16) __half sm[];
    __half* Ah = sm;                      // 128*72
    __half* Th = Ah + 128 * ASTRIDE;      // 128*72
    __half* Wh = Th + 128 * ASTRIDE;      // 64*72
    __shared__ float s_bias[256];

    const int tid  = threadIdx.x;
    const int wid  = tid >> 5;
    const int lane = tid & 31;
    const int row0 = blockIdx.x * 128;

    s_bias[tid] = g_bias[tid];

    // ---- A tile: plain fp16 copy of out1h rows ----
    {
        const int r    = tid >> 1;
        const int half = tid & 1;
        const int row  = row0 + r;
        uint4* aDst = (uint4*)((char*)(Ah + r * ASTRIDE) + half * 64);
        if (row < N) {
            const uint4* src = (const uint4*)(g_out1h + (size_t)row * D + half * 32);
#pragma unroll
            for (int j = 0; j < 4; ++j) aDst[j] = src[j];
        } else {
            const uint4 z = make_uint4(0, 0, 0, 0);
#pragma unroll
            for (int j = 0; j < 4; ++j) aDst[j] = z;
        }
    }

    const int m0 = (wid & 3) * 32;
    const int n0 = (wid >> 2) * 32;

    const uint32_t uAh = smem_u32(Ah);
    const uint32_t uTh = smem_u32(Th);
    const uint32_t uWh = smem_u32(Wh);
    const uint32_t arow = (uint32_t)(m0 + (lane & 15));
    const uint32_t acol = (uint32_t)((lane >> 4) * 8);
    const uint32_t aA0 = (arow * ASTRIDE + acol) * 2;
    const uint32_t aA1 = ((arow + 16) * ASTRIDE + acol) * 2;
    const uint32_t brow = (uint32_t)(n0 + (lane & 7) + ((lane >> 4) << 3));
    const uint32_t bcol = (uint32_t)(((lane >> 3) & 1) * 8);
    const uint32_t aB0 = (brow * ASTRIDE + bcol) * 2;
    const uint32_t aB1 = ((brow + 16) * ASTRIDE + bcol) * 2;

    float acc2[2][4][4];
#pragma unroll
    for (int mt = 0; mt < 2; ++mt)
#pragma unroll
        for (int nt = 0; nt < 4; ++nt)
#pragma unroll
            for (int e = 0; e < 4; ++e) acc2[mt][nt][e] = 0.f;

    const int ccol = n0 + (lane & 3) * 2;

    for (int cb4 = 0; cb4 < 4; ++cb4) {
        const int c0 = cb4 * 64;

        // ---- W2' chunk (8KB) ----
        {
            const uint4* sh = (const uint4*)(g_W2h + (size_t)c0 * 64);
            *(uint4*)((char*)(Wh + (tid >> 3) * ASTRIDE) + (tid & 7) * 16) = sh[tid];
            int f2 = tid + 256;
            *(uint4*)((char*)(Wh + (f2 >> 3) * ASTRIDE) + (f2 & 7) * 16) = sh[f2];
        }
        __syncthreads();

        // ---- GEMM1 chunk: acc1 = A @ W2'c + bias ----
        float acc1[2][4][4];
#pragma unroll
        for (int mt = 0; mt < 2; ++mt)
#pragma unroll
            for (int nt = 0; nt < 4; ++nt) {
                float b0 = s_bias[c0 + ccol + nt * 8];
                float b1 = s_bias[c0 + ccol + nt * 8 + 1];
                acc1[mt][nt][0] = b0; acc1[mt][nt][1] = b1;
                acc1[mt][nt][2] = b0; acc1[mt][nt][3] = b1;
            }

#pragma unroll
        for (int kk = 0; kk < 4; ++kk) {
            const uint32_t ko = kk * 32;
            uint32_t ah[8], bh[8];
            ldm_x4(ah,     uAh + aA0 + ko);
            ldm_x4(ah + 4, uAh + aA1 + ko);
            ldm_x4(bh,     uWh + aB0 + ko);
            ldm_x4(bh + 4, uWh + aB1 + ko);
#pragma unroll
            for (int mt = 0; mt < 2; ++mt)
#pragma unroll
                for (int nt = 0; nt < 4; ++nt)
                    mma_f16(acc1[mt][nt], ah + mt * 4, bh + nt * 2);
        }

        // ---- relu + fp16 -> T ----
#pragma unroll
        for (int mt = 0; mt < 2; ++mt) {
            int lr0 = m0 + mt * 16 + (lane >> 2);
            int lr1 = lr0 + 8;
#pragma unroll
            for (int nt = 0; nt < 4; ++nt) {
                __half2 h;
                h = __floats2half2_rn(fmaxf(acc1[mt][nt][0], 0.f),
                                      fmaxf(acc1[mt][nt][1], 0.f));
                *(__half2*)(Th + lr0 * ASTRIDE + ccol + nt * 8) = h;
                h = __floats2half2_rn(fmaxf(acc1[mt][nt][2], 0.f),
                                      fmaxf(acc1[mt][nt][3], 0.f));
                *(__half2*)(Th + lr1 * ASTRIDE + ccol + nt * 8) = h;
            }
        }
        __syncthreads();   // T visible; done with W2 chunk

        // ---- W3 chunk ----
        {
            int r = tid >> 3, c8 = tid & 7;
            *(uint4*)((char*)(Wh + r * ASTRIDE) + c8 * 16) =
                *((const uint4*)(g_W3h + (size_t)r * 256 + c0) + c8);
            int f2 = tid + 256;
            int r2 = f2 >> 3, c82 = f2 & 7;
            *(uint4*)((char*)(Wh + r2 * ASTRIDE) + c82 * 16) =
                *((const uint4*)(g_W3h + (size_t)r2 * 256 + c0) + c82);
        }
        __syncthreads();

        // ---- GEMM2 chunk: acc2 += T @ W3c ----
#pragma unroll
        for (int kk = 0; kk < 4; ++kk) {
            const uint32_t ko = kk * 32;
            uint32_t ah[8], bh[8];
            ldm_x4(ah,     uTh + aA0 + ko);
            ldm_x4(ah + 4, uTh + aA1 + ko);
            ldm_x4(bh,     uWh + aB0 + ko);
            ldm_x4(bh + 4, uWh + aB1 + ko);
#pragma unroll
            for (int mt = 0; mt < 2; ++mt)
#pragma unroll
                for (int nt = 0; nt < 4; ++nt)
                    mma_f16(acc2[mt][nt], ah + mt * 4, bh + nt * 2);
        }
        __syncthreads();
    }

    // ---- epilogue: residual + store ----
#pragma unroll
    for (int mt = 0; mt < 2; ++mt) {
        int r0 = row0 + m0 + mt * 16 + (lane >> 2);
        int r1 = r0 + 8;
        int cb = n0 + (lane & 3) * 2;
        if (r0 < N) {
            float* o = out + (size_t)r0 * D + cb;
            const float* xr = x + (size_t)r0 * D + cb;
#pragma unroll
            for (int nt = 0; nt < 4; ++nt) {
                float2 xv = *(const float2*)(xr + nt * 8);
                *(float2*)(o + nt * 8) =
                    make_float2(acc2[mt][nt][0] + xv.x, acc2[mt][nt][1] + xv.y);
            }
        }
        if (r1 < N) {
            float* o = out + (size_t)r1 * D + cb;
            const float* xr = x + (size_t)r1 * D + cb;
#pragma unroll
            for (int nt = 0; nt < 4; ++nt) {
                float2 xv = *(const float2*)(xr + nt * 8);
                *(float2*)(o + nt * 8) =
                    make_float2(acc2[mt][nt][2] + xv.x, acc2[mt][nt][3] + xv.y);
            }
        }
    }
}

// ============================================================
// launch
// ============================================================
extern "C" void kernel_launch(void* const* d_in, const int* in_sizes, int n_in,
                              void* d_out, int out_size)
{
    const float* x     = (const float*)d_in[0];
    const int*   nidx  = (const int*)  d_in[1];
    const int*   nmask = (const int*)  d_in[2];
    const float* W1    = (const float*)d_in[3];
    const float* gamma = (const float*)d_in[4];
    const float* beta  = (const float*)d_in[5];
    const float* W2    = (const float*)d_in[6];
    const float* W3    = (const float*)d_in[7];
    float* out = (float*)d_out;

    const int N = in_sizes[0] / D;
    const int K = in_sizes[1] / N;

    const int conv_smem = (256 * ASTRIDE + 64 * ASTRIDE) * 2;        // A + W
    cudaFuncSetAttribute(conv1_mma_kernel, cudaFuncAttributeMaxDynamicSharedMemorySize, conv_smem);
    const int mlp_smem = (128 * ASTRIDE * 2 + 64 * ASTRIDE) * 2;     // A + T + W
    cudaFuncSetAttribute(mlp_mma_kernel, cudaFuncAttributeMaxDynamicSharedMemorySize, mlp_smem);

    const int total8 = N * D / 8;
    prep_x_kernel<<<(total8 + 255) / 256, 256>>>(x, total8);
    prep_w_kernel<<<K, 256>>>(W1, W3, K);
    conv1_mma_kernel<<<(N + 255) / 256, 256, conv_smem>>>(nidx, nmask, N, K);
    finalize_kernel<<<1, 256>>>(gamma, beta, W2, 1.0f / (float)N);
    mlp_mma_kernel<<<(N + 127) / 128, 256, mlp_smem>>>(x, out, N);
}

// round 8
// speedup vs baseline: 4.3083x; 1.0933x over previous
#include <cuda_runtime.h>
#include <cuda_fp16.h>
#include <cstdint>

#define D 64
#define MAXN 150208
#define KMAX 27
#define ASTRIDE 72

// ---- scratch (static device arrays: allocation-free) ----
__device__ __half g_out1h[(size_t)MAXN * D];  // conv1 output (fp16)
__device__ float g_sum[D];
__device__ float g_sq[D];
__device__ float g_bias[256];                 // sh @ W2
__device__ __half g_xh[(size_t)MAXN * D];     // x rounded to fp16
__device__ __half g_W1h[(size_t)KMAX * 4096]; // W1^T [k][n][c] fp16
__device__ __half g_W2h[256 * 64];            // (sc*W2)^T [n][c] fp16 (post-BN fold)
__device__ __half g_W3h[64 * 256];            // W3^T [n][c] fp16

// ============================================================
// helpers
// ============================================================
__device__ __forceinline__ uint32_t smem_u32(const void* p) {
    uint32_t a;
    asm("{ .reg .u64 t; cvta.to.shared.u64 t, %1; cvt.u32.u64 %0, t; }" : "=r"(a) : "l"(p));
    return a;
}

__device__ __forceinline__ void ldm_x4(uint32_t* r, uint32_t addr) {
    asm volatile("ldmatrix.sync.aligned.m8n8.x4.shared.b16 {%0,%1,%2,%3}, [%4];"
                 : "=r"(r[0]), "=r"(r[1]), "=r"(r[2]), "=r"(r[3]) : "r"(addr));
}

__device__ __forceinline__ void mma_f16(float* d, const uint32_t* a, const uint32_t* b) {
    asm volatile(
        "mma.sync.aligned.m16n8k16.row.col.f32.f16.f16.f32 "
        "{%0,%1,%2,%3},{%4,%5,%6,%7},{%8,%9},{%0,%1,%2,%3};"
        : "+f"(d[0]), "+f"(d[1]), "+f"(d[2]), "+f"(d[3])
        : "r"(a[0]), "r"(a[1]), "r"(a[2]), "r"(a[3]), "r"(b[0]), "r"(b[1]));
}

__device__ __forceinline__ void cpa16(uint32_t dst, const void* src, uint32_t sz) {
    asm volatile("cp.async.cg.shared.global [%0], [%1], 16, %2;"
                 :: "r"(dst), "l"(src), "r"(sz) : "memory");
}
#define CPA_COMMIT() asm volatile("cp.async.commit_group;" ::: "memory")
#define CPA_WAIT0()  asm volatile("cp.async.wait_group 0;" ::: "memory")

// ============================================================
// prep kernels
// ============================================================
__global__ void prep_x_kernel(const float* __restrict__ x, int total8) {
    if (blockIdx.x == 0 && threadIdx.x < D) {
        g_sum[threadIdx.x] = 0.f;
        g_sq[threadIdx.x] = 0.f;
    }
    int e = blockIdx.x * blockDim.x + threadIdx.x;
    if (e >= total8) return;
    const float4* s = (const float4*)x + 2 * e;
    float4 a = s[0], b = s[1];
    uint4 o;
    __half2 h;
    h = __floats2half2_rn(a.x, a.y); o.x = *(uint32_t*)&h;
    h = __floats2half2_rn(a.z, a.w); o.y = *(uint32_t*)&h;
    h = __floats2half2_rn(b.x, b.y); o.z = *(uint32_t*)&h;
    h = __floats2half2_rn(b.z, b.w); o.w = *(uint32_t*)&h;
    ((uint4*)g_xh)[e] = o;
}

// W1[k][c][n] -> W1t[k][n][c] fp16;  W3[c][n] -> W3t[n][c] fp16
__global__ void prep_w_kernel(const float* __restrict__ W1,
                              const float* __restrict__ W3, int K) {
    int k = blockIdx.x;
    if (k < K) {
        const float* Wk = W1 + (size_t)k * 4096;
        __half* dh = g_W1h + (size_t)k * 4096;
        for (int e = threadIdx.x; e < 4096; e += blockDim.x) {
            int n = e >> 6, c = e & 63;
            dh[n * 64 + c] = __float2half_rn(Wk[c * 64 + n]);
        }
    }
    if (blockIdx.x == 0) {
        for (int e = threadIdx.x; e < 64 * 256; e += blockDim.x) {
            int n = e >> 8, c = e & 255;
            g_W3h[n * 256 + c] = __float2half_rn(W3[(size_t)c * 64 + n]);
        }
    }
}

// ============================================================
// conv1 via mma.sync fp16: 256x64 tile per CTA, 4 warps,
// warp tile 64x64 (4 m-tiles x 8 n8-tiles). cp.async loads.
// Accumulates per-channel BN stats (pad rows are exact zeros).
// ============================================================
__global__ __launch_bounds__(128, 2) void conv1_mma_kernel(
    const int*   __restrict__ nbr_idx,
    const int*   __restrict__ nbr_mask,
    int N, int K)
{
    extern __shared__ __align__(16) __half sm[];
    __half* Ah = sm;                      // 256*72
    __half* Wh = Ah + 256 * ASTRIDE;      // 64*72
    __shared__ float s_sum[D], s_sq[D];

    const int tid  = threadIdx.x;         // 0..127
    const int wid  = tid >> 5;            // 0..3
    const int lane = tid & 31;
    const int row0 = blockIdx.x * 256;

    if (tid < D) { s_sum[tid] = 0.f; s_sq[tid] = 0.f; }

    // gather: 2 rows per thread (tid and tid+128), 8 x 16B each
    const int gr0 = row0 + tid;
    const int gr1 = gr0 + 128;
    const uint32_t aSm0 = smem_u32(Ah + tid * ASTRIDE);
    const uint32_t aSm1 = smem_u32(Ah + (tid + 128) * ASTRIDE);

    // W tile: 512 16B-chunks, 4 per thread
    uint32_t wSm[4];
    const __half* wSrcBase[4];
#pragma unroll
    for (int j = 0; j < 4; ++j) {
        int f = tid + 128 * j;
        int r = f >> 3, c8 = f & 7;
        wSm[j] = smem_u32((char*)(Wh + r * ASTRIDE) + c8 * 16);
        wSrcBase[j] = (const __half*)0 + f * 8;   // offset only; add per-k base later
    }

    const int m0 = wid * 64;

    const uint32_t uAh = smem_u32(Ah);
    const uint32_t uWh = smem_u32(Wh);
    uint32_t aA[4];
#pragma unroll
    for (int mt = 0; mt < 4; ++mt)
        aA[mt] = (uint32_t)(((m0 + mt * 16 + (lane & 15)) * ASTRIDE + (lane >> 4) * 8) * 2);
    uint32_t aB[4];
#pragma unroll
    for (int nb = 0; nb < 4; ++nb)
        aB[nb] = (uint32_t)(((nb * 16 + (lane & 7) + ((lane >> 4) << 3)) * ASTRIDE
                             + ((lane >> 3) & 1) * 8) * 2);

    float acc[4][8][4];
#pragma unroll
    for (int mt = 0; mt < 4; ++mt)
#pragma unroll
        for (int nt = 0; nt < 8; ++nt)
#pragma unroll
            for (int e = 0; e < 4; ++e) acc[mt][nt][e] = 0.f;

    for (int k = 0; k < K; ++k) {
        // ---- W tile via cp.async (8KB) ----
        {
            const char* base = (const char*)(g_W1h + (size_t)k * 4096);
#pragma unroll
            for (int j = 0; j < 4; ++j)
                cpa16(wSm[j], base + (size_t)((tid + 128 * j) * 16), 16);
        }

        // ---- masked gather via cp.async (zfill when masked) ----
        {
            int m0g = 0, m1g = 0;
            const char *s0, *s1;
            if (gr0 < N) m0g = nbr_mask[(size_t)k * N + gr0];
            if (gr1 < N) m1g = nbr_mask[(size_t)k * N + gr1];
            s0 = (const char*)(g_xh + (size_t)(m0g ? nbr_idx[(size_t)k * N + gr0] : 0) * D);
            s1 = (const char*)(g_xh + (size_t)(m1g ? nbr_idx[(size_t)k * N + gr1] : 0) * D);
            uint32_t z0 = m0g ? 16u : 0u;
            uint32_t z1 = m1g ? 16u : 0u;
#pragma unroll
            for (int j = 0; j < 8; ++j) {
                cpa16(aSm0 + j * 16, s0 + j * 16, z0);
                cpa16(aSm1 + j * 16, s1 + j * 16, z1);
            }
        }
        CPA_COMMIT();
        CPA_WAIT0();
        __syncthreads();

        // ---- mma: 4 mt x 8 n8-tiles per kk ----
#pragma unroll
        for (int kk = 0; kk < 4; ++kk) {
            const uint32_t ko = kk * 32;
            uint32_t b[4][4];
#pragma unroll
            for (int nb = 0; nb < 4; ++nb)
                ldm_x4(b[nb], uWh + aB[nb] + ko);
#pragma unroll
            for (int mt = 0; mt < 4; ++mt) {
                uint32_t a[4];
                ldm_x4(a, uAh + aA[mt] + ko);
#pragma unroll
                for (int nb = 0; nb < 4; ++nb) {
                    mma_f16(acc[mt][2 * nb],     a, b[nb]);
                    mma_f16(acc[mt][2 * nb + 1], a, b[nb] + 2);
                }
            }
        }
        __syncthreads();
    }

    // ---- epilogue: fp16 store + BN-stat accumulation ----
    const int cb = (lane & 3) * 2;
#pragma unroll
    for (int mt = 0; mt < 4; ++mt) {
        int r0 = row0 + m0 + mt * 16 + (lane >> 2);
        int r1 = r0 + 8;
        if (r0 < N) {
            __half* o = g_out1h + (size_t)r0 * D + cb;
#pragma unroll
            for (int nt = 0; nt < 8; ++nt)
                *(__half2*)(o + nt * 8) = __floats2half2_rn(acc[mt][nt][0], acc[mt][nt][1]);
        }
        if (r1 < N) {
            __half* o = g_out1h + (size_t)r1 * D + cb;
#pragma unroll
            for (int nt = 0; nt < 8; ++nt)
                *(__half2*)(o + nt * 8) = __floats2half2_rn(acc[mt][nt][2], acc[mt][nt][3]);
        }
    }
    // stats: pad rows hold exact zeros -> safe unmasked
#pragma unroll
    for (int nt = 0; nt < 8; ++nt) {
        float cs0 = 0.f, cq0 = 0.f, cs1 = 0.f, cq1 = 0.f;
#pragma unroll
        for (int mt = 0; mt < 4; ++mt) {
            float a0 = acc[mt][nt][0], a2 = acc[mt][nt][2];
            float a1 = acc[mt][nt][1], a3 = acc[mt][nt][3];
            cs0 += a0 + a2; cq0 += a0 * a0 + a2 * a2;
            cs1 += a1 + a3; cq1 += a1 * a1 + a3 * a3;
        }
        atomicAdd(&s_sum[cb + nt * 8 + 0], cs0);
        atomicAdd(&s_sq [cb + nt * 8 + 0], cq0);
        atomicAdd(&s_sum[cb + nt * 8 + 1], cs1);
        atomicAdd(&s_sq [cb + nt * 8 + 1], cq1);
    }
    __syncthreads();
    if (tid < D) {
        atomicAdd(&g_sum[tid], s_sum[tid]);
        atomicAdd(&g_sq [tid], s_sq[tid]);
    }
}

// ============================================================
// finalize (parallel): BN -> fold into W2 (fp16) + bias vector
// grid 256 (one block per W2 output column), block 64.
// ============================================================
__global__ __launch_bounds__(64) void finalize_kernel(
    const float* __restrict__ gamma,
    const float* __restrict__ beta,
    const float* __restrict__ W2,
    float invN)
{
    __shared__ float red[2];
    const int c = threadIdx.x;   // input channel
    const int n = blockIdx.x;    // W2 output column
    float mean = g_sum[c] * invN;
    float var  = g_sq[c] * invN - mean * mean;
    float rstd = rsqrtf(var + 1e-5f);
    float sc   = rstd * gamma[c];
    float sh   = beta[c] - mean * sc;
    float w = W2[(size_t)c * 256 + n];
    g_W2h[n * 64 + c] = __float2half_rn(sc * w);
    float b = sh * w;
#pragma unroll
    for (int off = 16; off; off >>= 1) b += __shfl_down_sync(~0u, b, off);
    if ((c & 31) == 0) red[c >> 5] = b;
    __syncthreads();
    if (c == 0) g_bias[n] = red[0] + red[1];
}

// ============================================================
// fused MLP via mma.sync fp16: 128-row tile per CTA, 8 warps.
// out = relu(out1h @ W2' + bias) @ W3 + x
// ============================================================
__global__ __launch_bounds__(256) void mlp_mma_kernel(
    const float* __restrict__ x,
    float* __restrict__ out,
    int N)
{
    extern __shared__ __align__(16) __half sm[];
    __half* Ah = sm;                      // 128*72
    __half* Th = Ah + 128 * ASTRIDE;      // 128*72
    __half* Wh = Th + 128 * ASTRIDE;      // 64*72
    __shared__ float s_bias[256];

    const int tid  = threadIdx.x;
    const int wid  = tid >> 5;
    const int lane = tid & 31;
    const int row0 = blockIdx.x * 128;

    s_bias[tid] = g_bias[tid];

    // ---- A tile: plain fp16 copy of out1h rows ----
    {
        const int r    = tid >> 1;
        const int half = tid & 1;
        const int row  = row0 + r;
        uint4* aDst = (uint4*)((char*)(Ah + r * ASTRIDE) + half * 64);
        if (row < N) {
            const uint4* src = (const uint4*)(g_out1h + (size_t)row * D + half * 32);
#pragma unroll
            for (int j = 0; j < 4; ++j) aDst[j] = src[j];
        } else {
            const uint4 z = make_uint4(0, 0, 0, 0);
#pragma unroll
            for (int j = 0; j < 4; ++j) aDst[j] = z;
        }
    }

    const int m0 = (wid & 3) * 32;
    const int n0 = (wid >> 2) * 32;

    const uint32_t uAh = smem_u32(Ah);
    const uint32_t uTh = smem_u32(Th);
    const uint32_t uWh = smem_u32(Wh);
    const uint32_t arow = (uint32_t)(m0 + (lane & 15));
    const uint32_t acol = (uint32_t)((lane >> 4) * 8);
    const uint32_t aA0 = (arow * ASTRIDE + acol) * 2;
    const uint32_t aA1 = ((arow + 16) * ASTRIDE + acol) * 2;
    const uint32_t brow = (uint32_t)(n0 + (lane & 7) + ((lane >> 4) << 3));
    const uint32_t bcol = (uint32_t)(((lane >> 3) & 1) * 8);
    const uint32_t aB0 = (brow * ASTRIDE + bcol) * 2;
    const uint32_t aB1 = ((brow + 16) * ASTRIDE + bcol) * 2;

    float acc2[2][4][4];
#pragma unroll
    for (int mt = 0; mt < 2; ++mt)
#pragma unroll
        for (int nt = 0; nt < 4; ++nt)
#pragma unroll
            for (int e = 0; e < 4; ++e) acc2[mt][nt][e] = 0.f;

    const int ccol = n0 + (lane & 3) * 2;

    for (int cb4 = 0; cb4 < 4; ++cb4) {
        const int c0 = cb4 * 64;

        // ---- W2' chunk (8KB) ----
        {
            const uint4* sh = (const uint4*)(g_W2h + (size_t)c0 * 64);
            *(uint4*)((char*)(Wh + (tid >> 3) * ASTRIDE) + (tid & 7) * 16) = sh[tid];
            int f2 = tid + 256;
            *(uint4*)((char*)(Wh + (f2 >> 3) * ASTRIDE) + (f2 & 7) * 16) = sh[f2];
        }
        __syncthreads();

        // ---- GEMM1 chunk: acc1 = A @ W2'c + bias ----
        float acc1[2][4][4];
#pragma unroll
        for (int mt = 0; mt < 2; ++mt)
#pragma unroll
            for (int nt = 0; nt < 4; ++nt) {
                float b0 = s_bias[c0 + ccol + nt * 8];
                float b1 = s_bias[c0 + ccol + nt * 8 + 1];
                acc1[mt][nt][0] = b0; acc1[mt][nt][1] = b1;
                acc1[mt][nt][2] = b0; acc1[mt][nt][3] = b1;
            }

#pragma unroll
        for (int kk = 0; kk < 4; ++kk) {
            const uint32_t ko = kk * 32;
            uint32_t ah[8], bh[8];
            ldm_x4(ah,     uAh + aA0 + ko);
            ldm_x4(ah + 4, uAh + aA1 + ko);
            ldm_x4(bh,     uWh + aB0 + ko);
            ldm_x4(bh + 4, uWh + aB1 + ko);
#pragma unroll
            for (int mt = 0; mt < 2; ++mt)
#pragma unroll
                for (int nt = 0; nt < 4; ++nt)
                    mma_f16(acc1[mt][nt], ah + mt * 4, bh + nt * 2);
        }

        // ---- relu + fp16 -> T ----
#pragma unroll
        for (int mt = 0; mt < 2; ++mt) {
            int lr0 = m0 + mt * 16 + (lane >> 2);
            int lr1 = lr0 + 8;
#pragma unroll
            for (int nt = 0; nt < 4; ++nt) {
                __half2 h;
                h = __floats2half2_rn(fmaxf(acc1[mt][nt][0], 0.f),
                                      fmaxf(acc1[mt][nt][1], 0.f));
                *(__half2*)(Th + lr0 * ASTRIDE + ccol + nt * 8) = h;
                h = __floats2half2_rn(fmaxf(acc1[mt][nt][2], 0.f),
                                      fmaxf(acc1[mt][nt][3], 0.f));
                *(__half2*)(Th + lr1 * ASTRIDE + ccol + nt * 8) = h;
            }
        }
        __syncthreads();   // T visible; done with W2 chunk

        // ---- W3 chunk ----
        {
            int r = tid >> 3, c8 = tid & 7;
            *(uint4*)((char*)(Wh + r * ASTRIDE) + c8 * 16) =
                *((const uint4*)(g_W3h + (size_t)r * 256 + c0) + c8);
            int f2 = tid + 256;
            int r2 = f2 >> 3, c82 = f2 & 7;
            *(uint4*)((char*)(Wh + r2 * ASTRIDE) + c82 * 16) =
                *((const uint4*)(g_W3h + (size_t)r2 * 256 + c0) + c82);
        }
        __syncthreads();

        // ---- GEMM2 chunk: acc2 += T @ W3c ----
#pragma unroll
        for (int kk = 0; kk < 4; ++kk) {
            const uint32_t ko = kk * 32;
            uint32_t ah[8], bh[8];
            ldm_x4(ah,     uTh + aA0 + ko);
            ldm_x4(ah + 4, uTh + aA1 + ko);
            ldm_x4(bh,     uWh + aB0 + ko);
            ldm_x4(bh + 4, uWh + aB1 + ko);
#pragma unroll
            for (int mt = 0; mt < 2; ++mt)
#pragma unroll
                for (int nt = 0; nt < 4; ++nt)
                    mma_f16(acc2[mt][nt], ah + mt * 4, bh + nt * 2);
        }
        __syncthreads();
    }

    // ---- epilogue: residual + store ----
#pragma unroll
    for (int mt = 0; mt < 2; ++mt) {
        int r0 = row0 + m0 + mt * 16 + (lane >> 2);
        int r1 = r0 + 8;
        int cb = n0 + (lane & 3) * 2;
        if (r0 < N) {
            float* o = out + (size_t)r0 * D + cb;
            const float* xr = x + (size_t)r0 * D + cb;
#pragma unroll
            for (int nt = 0; nt < 4; ++nt) {
                float2 xv = *(const float2*)(xr + nt * 8);
                *(float2*)(o + nt * 8) =
                    make_float2(acc2[mt][nt][0] + xv.x, acc2[mt][nt][1] + xv.y);
            }
        }
        if (r1 < N) {
            float* o = out + (size_t)r1 * D + cb;
            const float* xr = x + (size_t)r1 * D + cb;
#pragma unroll
            for (int nt = 0; nt < 4; ++nt) {
                float2 xv = *(const float2*)(xr + nt * 8);
                *(float2*)(o + nt * 8) =
                    make_float2(acc2[mt][nt][2] + xv.x, acc2[mt][nt][3] + xv.y);
            }
        }
    }
}

// ============================================================
// launch
// ============================================================
extern "C" void kernel_launch(void* const* d_in, const int* in_sizes, int n_in,
                              void* d_out, int out_size)
{
    const float* x     = (const float*)d_in[0];
    const int*   nidx  = (const int*)  d_in[1];
    const int*   nmask = (const int*)  d_in[2];
    const float* W1    = (const float*)d_in[3];
    const float* gamma = (const float*)d_in[4];
    const float* beta  = (const float*)d_in[5];
    const float* W2    = (const float*)d_in[6];
    const float* W3    = (const float*)d_in[7];
    float* out = (float*)d_out;

    const int N = in_sizes[0] / D;
    const int K = in_sizes[1] / N;

    const int conv_smem = (256 * ASTRIDE + 64 * ASTRIDE) * 2;        // A + W
    cudaFuncSetAttribute(conv1_mma_kernel, cudaFuncAttributeMaxDynamicSharedMemorySize, conv_smem);
    const int mlp_smem = (128 * ASTRIDE * 2 + 64 * ASTRIDE) * 2;     // A + T + W
    cudaFuncSetAttribute(mlp_mma_kernel, cudaFuncAttributeMaxDynamicSharedMemorySize, mlp_smem);

    const int total8 = N * D / 8;
    prep_x_kernel<<<(total8 + 255) / 256, 256>>>(x, total8);
    prep_w_kernel<<<K, 256>>>(W1, W3, K);
    conv1_mma_kernel<<<(N + 255) / 256, 128, conv_smem>>>(nidx, nmask, N, K);
    finalize_kernel<<<256, 64>>>(gamma, beta, W2, 1.0f / (float)N);
    mlp_mma_kernel<<<(N + 127) / 128, 256, mlp_smem>>>(x, out, N);
}

// round 9
// speedup vs baseline: 4.4309x; 1.0285x over previous
#include <cuda_runtime.h>
#include <cuda_fp16.h>
#include <cstdint>

#define D 64
#define MAXN 150208
#define KMAX 27
#define ASTRIDE 72

// ---- scratch (static device arrays: allocation-free) ----
__device__ __half g_out1h[(size_t)MAXN * D];  // conv1 output (fp16)
__device__ float g_sum[D];
__device__ float g_sq[D];
__device__ float g_bias[256];                 // sh @ W2
__device__ __half g_xh[(size_t)MAXN * D];     // x rounded to fp16
__device__ __half g_W1h[(size_t)KMAX * 4096]; // W1^T [k][n][c] fp16
__device__ __half g_W2h[256 * 64];            // (sc*W2)^T [n][c] fp16 (post-BN fold)
__device__ __half g_W3h[64 * 256];            // W3^T [n][c] fp16

// ============================================================
// helpers
// ============================================================
__device__ __forceinline__ uint32_t smem_u32(const void* p) {
    uint32_t a;
    asm("{ .reg .u64 t; cvta.to.shared.u64 t, %1; cvt.u32.u64 %0, t; }" : "=r"(a) : "l"(p));
    return a;
}

__device__ __forceinline__ void ldm_x4(uint32_t* r, uint32_t addr) {
    asm volatile("ldmatrix.sync.aligned.m8n8.x4.shared.b16 {%0,%1,%2,%3}, [%4];"
                 : "=r"(r[0]), "=r"(r[1]), "=r"(r[2]), "=r"(r[3]) : "r"(addr));
}

__device__ __forceinline__ void mma_f16(float* d, const uint32_t* a, const uint32_t* b) {
    asm volatile(
        "mma.sync.aligned.m16n8k16.row.col.f32.f16.f16.f32 "
        "{%0,%1,%2,%3},{%4,%5,%6,%7},{%8,%9},{%0,%1,%2,%3};"
        : "+f"(d[0]), "+f"(d[1]), "+f"(d[2]), "+f"(d[3])
        : "r"(a[0]), "r"(a[1]), "r"(a[2]), "r"(a[3]), "r"(b[0]), "r"(b[1]));
}

__device__ __forceinline__ void cpa16(uint32_t dst, const void* src, uint32_t sz) {
    asm volatile("cp.async.cg.shared.global [%0], [%1], 16, %2;"
                 :: "r"(dst), "l"(src), "r"(sz) : "memory");
}
#define CPA_COMMIT() asm volatile("cp.async.commit_group;" ::: "memory")
#define CPA_WAIT0()  asm volatile("cp.async.wait_group 0;" ::: "memory")
#define CPA_WAIT1()  asm volatile("cp.async.wait_group 1;" ::: "memory")

// ============================================================
// prep kernels
// ============================================================
__global__ void prep_x_kernel(const float* __restrict__ x, int total8) {
    if (blockIdx.x == 0 && threadIdx.x < D) {
        g_sum[threadIdx.x] = 0.f;
        g_sq[threadIdx.x] = 0.f;
    }
    int e = blockIdx.x * blockDim.x + threadIdx.x;
    if (e >= total8) return;
    const float4* s = (const float4*)x + 2 * e;
    float4 a = s[0], b = s[1];
    uint4 o;
    __half2 h;
    h = __floats2half2_rn(a.x, a.y); o.x = *(uint32_t*)&h;
    h = __floats2half2_rn(a.z, a.w); o.y = *(uint32_t*)&h;
    h = __floats2half2_rn(b.x, b.y); o.z = *(uint32_t*)&h;
    h = __floats2half2_rn(b.z, b.w); o.w = *(uint32_t*)&h;
    ((uint4*)g_xh)[e] = o;
}

// W1[k][c][n] -> W1t[k][n][c] fp16;  W3[c][n] -> W3t[n][c] fp16
__global__ void prep_w_kernel(const float* __restrict__ W1,
                              const float* __restrict__ W3, int K) {
    int k = blockIdx.x;
    if (k < K) {
        const float* Wk = W1 + (size_t)k * 4096;
        __half* dh = g_W1h + (size_t)k * 4096;
        for (int e = threadIdx.x; e < 4096; e += blockDim.x) {
            int n = e >> 6, c = e & 63;
            dh[n * 64 + c] = __float2half_rn(Wk[c * 64 + n]);
        }
    }
    if (blockIdx.x == 0) {
        for (int e = threadIdx.x; e < 64 * 256; e += blockDim.x) {
            int n = e >> 8, c = e & 255;
            g_W3h[n * 256 + c] = __float2half_rn(W3[(size_t)c * 64 + n]);
        }
    }
}

// ============================================================
// conv1 via mma.sync fp16: 256x64 tile per CTA, 4 warps,
// warp tile 64x64. Double-buffered cp.async pipeline.
// Accumulates per-channel BN stats (pad rows are exact zeros).
// ============================================================
#define STAGE_HALVES ((256 + 64) * ASTRIDE)   // A + W, halves per stage
__global__ __launch_bounds__(128, 2) void conv1_mma_kernel(
    const int*   __restrict__ nbr_idx,
    const int*   __restrict__ nbr_mask,
    int N, int K)
{
    extern __shared__ __align__(16) __half sm[];
    // stage s: A at sm + s*STAGE_HALVES, W at sm + s*STAGE_HALVES + 256*ASTRIDE
    __shared__ float s_sum[D], s_sq[D];

    const int tid  = threadIdx.x;         // 0..127
    const int wid  = tid >> 5;            // 0..3
    const int lane = tid & 31;
    const int row0 = blockIdx.x * 256;

    if (tid < D) { s_sum[tid] = 0.f; s_sq[tid] = 0.f; }

    const int gr0 = row0 + tid;
    const int gr1 = gr0 + 128;
    const uint32_t uBase = smem_u32(sm);
    const uint32_t stageB = STAGE_HALVES * 2;   // bytes per stage

    // per-thread smem write addresses within stage 0
    const uint32_t aSm0 = uBase + (uint32_t)(tid * ASTRIDE) * 2;
    const uint32_t aSm1 = uBase + (uint32_t)((tid + 128) * ASTRIDE) * 2;
    uint32_t wSm[4];
#pragma unroll
    for (int j = 0; j < 4; ++j) {
        int f = tid + 128 * j;
        wSm[j] = uBase + (uint32_t)(256 * ASTRIDE + (f >> 3) * ASTRIDE) * 2 + (f & 7) * 16;
    }

    const int m0 = wid * 64;
    uint32_t aA[4];
#pragma unroll
    for (int mt = 0; mt < 4; ++mt)
        aA[mt] = uBase + (uint32_t)(((m0 + mt * 16 + (lane & 15)) * ASTRIDE
                                     + (lane >> 4) * 8) * 2);
    uint32_t aB[4];
#pragma unroll
    for (int nb = 0; nb < 4; ++nb)
        aB[nb] = uBase + (uint32_t)((256 * ASTRIDE
                  + (nb * 16 + (lane & 7) + ((lane >> 4) << 3)) * ASTRIDE
                  + ((lane >> 3) & 1) * 8) * 2);

    float acc[4][8][4];
#pragma unroll
    for (int mt = 0; mt < 4; ++mt)
#pragma unroll
        for (int nt = 0; nt < 8; ++nt)
#pragma unroll
            for (int e = 0; e < 4; ++e) acc[mt][nt][e] = 0.f;

    // ---- pipeline load issue for offset k into stage s ----
    auto issue = [&](int k, int s) {
        const uint32_t so = (uint32_t)s * stageB;
        // W tile (8KB)
        const char* base = (const char*)(g_W1h + (size_t)k * 4096);
#pragma unroll
        for (int j = 0; j < 4; ++j)
            cpa16(wSm[j] + so, base + (size_t)((tid + 128 * j) * 16), 16);
        // masked gather (zfill when masked)
        int m0g = 0, m1g = 0;
        if (gr0 < N) m0g = nbr_mask[(size_t)k * N + gr0];
        if (gr1 < N) m1g = nbr_mask[(size_t)k * N + gr1];
        const char* s0 = (const char*)(g_xh + (size_t)(m0g ? nbr_idx[(size_t)k * N + gr0] : 0) * D);
        const char* s1 = (const char*)(g_xh + (size_t)(m1g ? nbr_idx[(size_t)k * N + gr1] : 0) * D);
        uint32_t z0 = m0g ? 16u : 0u;
        uint32_t z1 = m1g ? 16u : 0u;
#pragma unroll
        for (int j = 0; j < 8; ++j) {
            cpa16(aSm0 + so + j * 16, s0 + j * 16, z0);
            cpa16(aSm1 + so + j * 16, s1 + j * 16, z1);
        }
        CPA_COMMIT();
    };

    issue(0, 0);

    for (int k = 0; k < K; ++k) {
        const int s = k & 1;
        if (k + 1 < K) { issue(k + 1, s ^ 1); CPA_WAIT1(); }
        else           { CPA_WAIT0(); }
        __syncthreads();

        const uint32_t so = (uint32_t)s * stageB;
#pragma unroll
        for (int kk = 0; kk < 4; ++kk) {
            const uint32_t ko = kk * 32;
            uint32_t b[4][4];
#pragma unroll
            for (int nb = 0; nb < 4; ++nb)
                ldm_x4(b[nb], aB[nb] + so + ko);
#pragma unroll
            for (int mt = 0; mt < 4; ++mt) {
                uint32_t a[4];
                ldm_x4(a, aA[mt] + so + ko);
#pragma unroll
                for (int nb = 0; nb < 4; ++nb) {
                    mma_f16(acc[mt][2 * nb],     a, b[nb]);
                    mma_f16(acc[mt][2 * nb + 1], a, b[nb] + 2);
                }
            }
        }
        __syncthreads();   // all warps done with stage s before it is refilled
    }

    // ---- epilogue: fp16 store + BN-stat accumulation ----
    const int cb = (lane & 3) * 2;
#pragma unroll
    for (int mt = 0; mt < 4; ++mt) {
        int r0 = row0 + m0 + mt * 16 + (lane >> 2);
        int r1 = r0 + 8;
        if (r0 < N) {
            __half* o = g_out1h + (size_t)r0 * D + cb;
#pragma unroll
            for (int nt = 0; nt < 8; ++nt)
                *(__half2*)(o + nt * 8) = __floats2half2_rn(acc[mt][nt][0], acc[mt][nt][1]);
        }
        if (r1 < N) {
            __half* o = g_out1h + (size_t)r1 * D + cb;
#pragma unroll
            for (int nt = 0; nt < 8; ++nt)
                *(__half2*)(o + nt * 8) = __floats2half2_rn(acc[mt][nt][2], acc[mt][nt][3]);
        }
    }
    // stats: pad rows hold exact zeros -> safe unmasked
#pragma unroll
    for (int nt = 0; nt < 8; ++nt) {
        float cs0 = 0.f, cq0 = 0.f, cs1 = 0.f, cq1 = 0.f;
#pragma unroll
        for (int mt = 0; mt < 4; ++mt) {
            float a0 = acc[mt][nt][0], a2 = acc[mt][nt][2];
            float a1 = acc[mt][nt][1], a3 = acc[mt][nt][3];
            cs0 += a0 + a2; cq0 += a0 * a0 + a2 * a2;
            cs1 += a1 + a3; cq1 += a1 * a1 + a3 * a3;
        }
        atomicAdd(&s_sum[cb + nt * 8 + 0], cs0);
        atomicAdd(&s_sq [cb + nt * 8 + 0], cq0);
        atomicAdd(&s_sum[cb + nt * 8 + 1], cs1);
        atomicAdd(&s_sq [cb + nt * 8 + 1], cq1);
    }
    __syncthreads();
    if (tid < D) {
        atomicAdd(&g_sum[tid], s_sum[tid]);
        atomicAdd(&g_sq [tid], s_sq[tid]);
    }
}

// ============================================================
// finalize (parallel): BN -> fold into W2 (fp16) + bias vector
// ============================================================
__global__ __launch_bounds__(64) void finalize_kernel(
    const float* __restrict__ gamma,
    const float* __restrict__ beta,
    const float* __restrict__ W2,
    float invN)
{
    __shared__ float red[2];
    const int c = threadIdx.x;   // input channel
    const int n = blockIdx.x;    // W2 output column
    float mean = g_sum[c] * invN;
    float var  = g_sq[c] * invN - mean * mean;
    float rstd = rsqrtf(var + 1e-5f);
    float sc   = rstd * gamma[c];
    float sh   = beta[c] - mean * sc;
    float w = W2[(size_t)c * 256 + n];
    g_W2h[n * 64 + c] = __float2half_rn(sc * w);
    float b = sh * w;
#pragma unroll
    for (int off = 16; off; off >>= 1) b += __shfl_down_sync(~0u, b, off);
    if ((c & 31) == 0) red[c >> 5] = b;
    __syncthreads();
    if (c == 0) g_bias[n] = red[0] + red[1];
}

// ============================================================
// fused MLP via mma.sync fp16: 128-row tile per CTA, 8 warps.
// out = relu(out1h @ W2' + bias) @ W3 + x
// ============================================================
__global__ __launch_bounds__(256) void mlp_mma_kernel(
    const float* __restrict__ x,
    float* __restrict__ out,
    int N)
{
    extern __shared__ __align__(16) __half sm[];
    __half* Ah = sm;                      // 128*72
    __half* Th = Ah + 128 * ASTRIDE;      // 128*72
    __half* Wh = Th + 128 * ASTRIDE;      // 64*72
    __shared__ float s_bias[256];

    const int tid  = threadIdx.x;
    const int wid  = tid >> 5;
    const int lane = tid & 31;
    const int row0 = blockIdx.x * 128;

    s_bias[tid] = g_bias[tid];

    // ---- A tile: plain fp16 copy of out1h rows ----
    {
        const int r    = tid >> 1;
        const int half = tid & 1;
        const int row  = row0 + r;
        uint4* aDst = (uint4*)((char*)(Ah + r * ASTRIDE) + half * 64);
        if (row < N) {
            const uint4* src = (const uint4*)(g_out1h + (size_t)row * D + half * 32);
#pragma unroll
            for (int j = 0; j < 4; ++j) aDst[j] = src[j];
        } else {
            const uint4 z = make_uint4(0, 0, 0, 0);
#pragma unroll
            for (int j = 0; j < 4; ++j) aDst[j] = z;
        }
    }

    const int m0 = (wid & 3) * 32;
    const int n0 = (wid >> 2) * 32;

    const uint32_t uAh = smem_u32(Ah);
    const uint32_t uTh = smem_u32(Th);
    const uint32_t uWh = smem_u32(Wh);
    const uint32_t arow = (uint32_t)(m0 + (lane & 15));
    const uint32_t acol = (uint32_t)((lane >> 4) * 8);
    const uint32_t aA0 = (arow * ASTRIDE + acol) * 2;
    const uint32_t aA1 = ((arow + 16) * ASTRIDE + acol) * 2;
    const uint32_t brow = (uint32_t)(n0 + (lane & 7) + ((lane >> 4) << 3));
    const uint32_t bcol = (uint32_t)(((lane >> 3) & 1) * 8);
    const uint32_t aB0 = (brow * ASTRIDE + bcol) * 2;
    const uint32_t aB1 = ((brow + 16) * ASTRIDE + bcol) * 2;

    float acc2[2][4][4];
#pragma unroll
    for (int mt = 0; mt < 2; ++mt)
#pragma unroll
        for (int nt = 0; nt < 4; ++nt)
#pragma unroll
            for (int e = 0; e < 4; ++e) acc2[mt][nt][e] = 0.f;

    const int ccol = n0 + (lane & 3) * 2;

    for (int cb4 = 0; cb4 < 4; ++cb4) {
        const int c0 = cb4 * 64;

        // ---- W2' chunk (8KB) ----
        {
            const uint4* sh = (const uint4*)(g_W2h + (size_t)c0 * 64);
            *(uint4*)((char*)(Wh + (tid >> 3) * ASTRIDE) + (tid & 7) * 16) = sh[tid];
            int f2 = tid + 256;
            *(uint4*)((char*)(Wh + (f2 >> 3) * ASTRIDE) + (f2 & 7) * 16) = sh[f2];
        }
        __syncthreads();

        // ---- GEMM1 chunk: acc1 = A @ W2'c + bias ----
        float acc1[2][4][4];
#pragma unroll
        for (int mt = 0; mt < 2; ++mt)
#pragma unroll
            for (int nt = 0; nt < 4; ++nt) {
                float b0 = s_bias[c0 + ccol + nt * 8];
                float b1 = s_bias[c0 + ccol + nt * 8 + 1];
                acc1[mt][nt][0] = b0; acc1[mt][nt][1] = b1;
                acc1[mt][nt][2] = b0; acc1[mt][nt][3] = b1;
            }

#pragma unroll
        for (int kk = 0; kk < 4; ++kk) {
            const uint32_t ko = kk * 32;
            uint32_t ah[8], bh[8];
            ldm_x4(ah,     uAh + aA0 + ko);
            ldm_x4(ah + 4, uAh + aA1 + ko);
            ldm_x4(bh,     uWh + aB0 + ko);
            ldm_x4(bh + 4, uWh + aB1 + ko);
#pragma unroll
            for (int mt = 0; mt < 2; ++mt)
#pragma unroll
                for (int nt = 0; nt < 4; ++nt)
                    mma_f16(acc1[mt][nt], ah + mt * 4, bh + nt * 2);
        }

        // ---- relu + fp16 -> T ----
#pragma unroll
        for (int mt = 0; mt < 2; ++mt) {
            int lr0 = m0 + mt * 16 + (lane >> 2);
            int lr1 = lr0 + 8;
#pragma unroll
            for (int nt = 0; nt < 4; ++nt) {
                __half2 h;
                h = __floats2half2_rn(fmaxf(acc1[mt][nt][0], 0.f),
                                      fmaxf(acc1[mt][nt][1], 0.f));
                *(__half2*)(Th + lr0 * ASTRIDE + ccol + nt * 8) = h;
                h = __floats2half2_rn(fmaxf(acc1[mt][nt][2], 0.f),
                                      fmaxf(acc1[mt][nt][3], 0.f));
                *(__half2*)(Th + lr1 * ASTRIDE + ccol + nt * 8) = h;
            }
        }
        __syncthreads();   // T visible; done with W2 chunk

        // ---- W3 chunk ----
        {
            int r = tid >> 3, c8 = tid & 7;
            *(uint4*)((char*)(Wh + r * ASTRIDE) + c8 * 16) =
                *((const uint4*)(g_W3h + (size_t)r * 256 + c0) + c8);
            int f2 = tid + 256;
            int r2 = f2 >> 3, c82 = f2 & 7;
            *(uint4*)((char*)(Wh + r2 * ASTRIDE) + c82 * 16) =
                *((const uint4*)(g_W3h + (size_t)r2 * 256 + c0) + c82);
        }
        __syncthreads();

        // ---- GEMM2 chunk: acc2 += T @ W3c ----
#pragma unroll
        for (int kk = 0; kk < 4; ++kk) {
            const uint32_t ko = kk * 32;
            uint32_t ah[8], bh[8];
            ldm_x4(ah,     uTh + aA0 + ko);
            ldm_x4(ah + 4, uTh + aA1 + ko);
            ldm_x4(bh,     uWh + aB0 + ko);
            ldm_x4(bh + 4, uWh + aB1 + ko);
#pragma unroll
            for (int mt = 0; mt < 2; ++mt)
#pragma unroll
                for (int nt = 0; nt < 4; ++nt)
                    mma_f16(acc2[mt][nt], ah + mt * 4, bh + nt * 2);
        }
        __syncthreads();
    }

    // ---- epilogue: residual + store ----
#pragma unroll
    for (int mt = 0; mt < 2; ++mt) {
        int r0 = row0 + m0 + mt * 16 + (lane >> 2);
        int r1 = r0 + 8;
        int cb = n0 + (lane & 3) * 2;
        if (r0 < N) {
            float* o = out + (size_t)r0 * D + cb;
            const float* xr = x + (size_t)r0 * D + cb;
#pragma unroll
            for (int nt = 0; nt < 4; ++nt) {
                float2 xv = *(const float2*)(xr + nt * 8);
                *(float2*)(o + nt * 8) =
                    make_float2(acc2[mt][nt][0] + xv.x, acc2[mt][nt][1] + xv.y);
            }
        }
        if (r1 < N) {
            float* o = out + (size_t)r1 * D + cb;
            const float* xr = x + (size_t)r1 * D + cb;
#pragma unroll
            for (int nt = 0; nt < 4; ++nt) {
                float2 xv = *(const float2*)(xr + nt * 8);
                *(float2*)(o + nt * 8) =
                    make_float2(acc2[mt][nt][2] + xv.x, acc2[mt][nt][3] + xv.y);
            }
        }
    }
}

// ============================================================
// launch
// ============================================================
extern "C" void kernel_launch(void* const* d_in, const int* in_sizes, int n_in,
                              void* d_out, int out_size)
{
    const float* x     = (const float*)d_in[0];
    const int*   nidx  = (const int*)  d_in[1];
    const int*   nmask = (const int*)  d_in[2];
    const float* W1    = (const float*)d_in[3];
    const float* gamma = (const float*)d_in[4];
    const float* beta  = (const float*)d_in[5];
    const float* W2    = (const float*)d_in[6];
    const float* W3    = (const float*)d_in[7];
    float* out = (float*)d_out;

    const int N = in_sizes[0] / D;
    const int K = in_sizes[1] / N;

    const int conv_smem = STAGE_HALVES * 2 * 2;                      // 2 stages
    cudaFuncSetAttribute(conv1_mma_kernel, cudaFuncAttributeMaxDynamicSharedMemorySize, conv_smem);
    const int mlp_smem = (128 * ASTRIDE * 2 + 64 * ASTRIDE) * 2;     // A + T + W
    cudaFuncSetAttribute(mlp_mma_kernel, cudaFuncAttributeMaxDynamicSharedMemorySize, mlp_smem);

    const int total8 = N * D / 8;
    prep_x_kernel<<<(total8 + 255) / 256, 256>>>(x, total8);
    prep_w_kernel<<<K, 256>>>(W1, W3, K);
    conv1_mma_kernel<<<(N + 255) / 256, 128, conv_smem>>>(nidx, nmask, N, K);
    finalize_kernel<<<256, 64>>>(gamma, beta, W2, 1.0f / (float)N);
    mlp_mma_kernel<<<(N + 127) / 128, 256, mlp_smem>>>(x, out, N);
}